// round 9
// baseline (speedup 1.0000x reference)
#include <cuda_runtime.h>
#include <cuda_bf16.h>
#include <cstdint>

// 2-layer LSTM, B=4096, H=300, T=64, tcgen05 bf16-split MMA, pipelined.
// Per cell: gates[4096,1200] = X@Wih^T + H@Whh^T (+bias). D in TMEM fp32,
// 3 split products (hi*hi, hi*lo, lo*hi). Weights pre-split, gate-interleaved
// (col n = 4*h + gate). Each CTA: M=128, N=240 (two N=120 MMAs), K streamed
// through 2 smem stages with commit-deferred double buffering.

#if defined(__CUDA_ARCH_FEAT_SM103_ALL) || defined(__CUDA_ARCH_FEAT_SM100_ALL) || \
    defined(__CUDA_ARCH_FEAT_SM101_ALL) ||                                        \
    (defined(__CUDA_ARCH_FAMILY_SPECIFIC__) && (__CUDA_ARCH_FAMILY_SPECIFIC__ >= 1000))
#define LSTM_TC 1
#else
#define LSTM_TC 0
#endif

#define SW128(o) ((o) ^ (((o) >> 3) & 0x70))

namespace {
constexpr int Bx = 4096, Hd = 300, Tn = 64;
constexpr int Kp = 320;              // K per phase, padded (300 -> 5*64)
constexpr int Np = 1200;             // 4*Hd, gate-interleaved
constexpr int BM = 128, BN = 240, BK = 64;
constexpr int NH = BN / 4;           // 60 h-groups per CTA
constexpr int NKT = Kp / BK;         // 5 (per phase); 10 iterations total
constexpr int NMT = Bx / BM;         // 32
constexpr int NNT = Np / BN;         // 5
constexpr unsigned IDESC = (1u << 4)      // dtype F32
                         | (1u << 7)      // atype BF16
                         | (1u << 10)     // btype BF16
                         | ((120 / 8) << 17)   // N=120 per MMA
                         | ((BM / 16) << 24);
constexpr unsigned long long DESC_BASE =  // SW128, Blackwell, SBO=64, LBO=1
    (2ull << 61) | (1ull << 46) | (64ull << 32) | (1ull << 16);
// smem layout
constexpr int SM_TMEM = 0;
constexpr int SM_MBAR = 8;            // two mbars: 8, 16
constexpr int SM_BIAS = 64;           // 240 floats
constexpr int ST_A_HI = 0;            // within a stage
constexpr int ST_A_LO = 16384;
constexpr int ST_B_HI = 32768;        // 240*128 = 30720
constexpr int ST_B_LO = 63488;
constexpr int STAGE_SZ = 94208;       // 92 KiB, 1024-aligned
constexpr int SM_STAGE0 = 1024;
constexpr int SM_TOTAL = SM_STAGE0 + 2 * STAGE_SZ;  // 189440
// epilogue staging (reuses stage 0 after mainloop)
constexpr int EP_HHI = SM_STAGE0;                  // bf16[128*60]
constexpr int EP_HLO = EP_HHI + BM * NH * 2;
constexpr int EP_Y   = EP_HLO + BM * NH * 2;       // float[128*60]
}

// ---- persistent device state -------------------------------------------
__device__ __align__(1024) __nv_bfloat16 g_WHi[4][Np * Kp];  // ih0,hh0,ih1,hh1
__device__ __align__(1024) __nv_bfloat16 g_WLo[4][Np * Kp];
__device__ float g_bias[2][Np];
__device__ __align__(1024) __nv_bfloat16 g_zHi[Bx * Kp];
__device__ __align__(1024) __nv_bfloat16 g_zLo[Bx * Kp];
__device__ __align__(1024) __nv_bfloat16 g_hHi[2][2][Bx * Kp];  // [layer][buf]
__device__ __align__(1024) __nv_bfloat16 g_hLo[2][2][Bx * Kp];
__device__ float g_c[2][Hd * Bx];  // [cell][h*Bx + m] (transposed, coalesced)

// ---- small helpers ------------------------------------------------------
__device__ __forceinline__ float sigmoid_f(float v) {
  return __fdividef(1.0f, 1.0f + __expf(-v));
}
__device__ __forceinline__ float tanh_f(float v) {
  return 2.0f * __fdividef(1.0f, 1.0f + __expf(-2.0f * v)) - 1.0f;
}

#if LSTM_TC
__device__ __forceinline__ void mma_f16_ss(uint32_t d, unsigned long long da,
                                           unsigned long long db, uint32_t en) {
  asm volatile(
      "{\n\t.reg .pred p;\n\tsetp.ne.u32 p, %4, 0;\n\t"
      "tcgen05.mma.cta_group::1.kind::f16 [%0], %1, %2, %3, {%5, %5, %5, %5}, p;\n\t}"
      :: "r"(d), "l"(da), "l"(db), "r"(IDESC), "r"(en), "r"(0u) : "memory");
}

__device__ __forceinline__ void mbar_wait(uint32_t mbar, uint32_t parity) {
  uint32_t done;
  asm volatile(
      "{\n\t.reg .pred p;\n\t"
      "mbarrier.try_wait.parity.acquire.cta.shared::cta.b64 p, [%1], %2;\n\t"
      "selp.b32 %0, 1, 0, p;\n\t}"
      : "=r"(done) : "r"(mbar), "r"(parity) : "memory");
  if (!done) {
    asm volatile(
        "{\n\t.reg .pred P1;\n\t"
        "W_%=:\n\t"
        "mbarrier.try_wait.parity.acquire.cta.shared::cta.b64 P1, [%0], %1, 0x989680;\n\t"
        "@P1 bra.uni D_%=;\n\t"
        "bra.uni W_%=;\n\t"
        "D_%=:\n\t}"
        :: "r"(mbar), "r"(parity) : "memory");
  }
}

__device__ __forceinline__ void ldtm_x32(uint32_t* r, uint32_t a) {
  asm volatile(
      "tcgen05.ld.sync.aligned.32x32b.x32.b32 "
      "{%0,%1,%2,%3,%4,%5,%6,%7,%8,%9,%10,%11,%12,%13,%14,%15,"
      "%16,%17,%18,%19,%20,%21,%22,%23,%24,%25,%26,%27,%28,%29,%30,%31}, [%32];"
      : "=r"(r[0]), "=r"(r[1]), "=r"(r[2]), "=r"(r[3]), "=r"(r[4]), "=r"(r[5]),
        "=r"(r[6]), "=r"(r[7]), "=r"(r[8]), "=r"(r[9]), "=r"(r[10]), "=r"(r[11]),
        "=r"(r[12]), "=r"(r[13]), "=r"(r[14]), "=r"(r[15]), "=r"(r[16]),
        "=r"(r[17]), "=r"(r[18]), "=r"(r[19]), "=r"(r[20]), "=r"(r[21]),
        "=r"(r[22]), "=r"(r[23]), "=r"(r[24]), "=r"(r[25]), "=r"(r[26]),
        "=r"(r[27]), "=r"(r[28]), "=r"(r[29]), "=r"(r[30]), "=r"(r[31])
      : "r"(a));
}
__device__ __forceinline__ void ldtm_x16(uint32_t* r, uint32_t a) {
  asm volatile(
      "tcgen05.ld.sync.aligned.32x32b.x16.b32 "
      "{%0,%1,%2,%3,%4,%5,%6,%7,%8,%9,%10,%11,%12,%13,%14,%15}, [%16];"
      : "=r"(r[0]), "=r"(r[1]), "=r"(r[2]), "=r"(r[3]), "=r"(r[4]), "=r"(r[5]),
        "=r"(r[6]), "=r"(r[7]), "=r"(r[8]), "=r"(r[9]), "=r"(r[10]), "=r"(r[11]),
        "=r"(r[12]), "=r"(r[13]), "=r"(r[14]), "=r"(r[15])
      : "r"(a));
}
#endif  // LSTM_TC

// ---- prep: split/pad weights, biases, z; zero state ---------------------
__global__ void prep_kernel(const float* __restrict__ z,
                            const float* __restrict__ Wih0,
                            const float* __restrict__ Whh0,
                            const float* __restrict__ bih0,
                            const float* __restrict__ bhh0,
                            const float* __restrict__ Wih1,
                            const float* __restrict__ Whh1,
                            const float* __restrict__ bih1,
                            const float* __restrict__ bhh1) {
  const int stride = gridDim.x * blockDim.x;
  const int g0 = blockIdx.x * blockDim.x + threadIdx.x;
  const float* Ws[4] = {Wih0, Whh0, Wih1, Whh1};
  for (int idx = g0; idx < 4 * Np * Kp; idx += stride) {
    int k = idx % Kp;
    int rr = idx / Kp;
    int n = rr % Np;
    int mi = rr / Np;
    int h = n >> 2, gg = n & 3;
    float w = (k < Hd) ? Ws[mi][(gg * Hd + h) * Hd + k] : 0.f;
    __nv_bfloat16 hi = __float2bfloat16(w);
    g_WHi[mi][n * Kp + k] = hi;
    g_WLo[mi][n * Kp + k] = __float2bfloat16(w - __bfloat162float(hi));
  }
  for (int idx = g0; idx < 2 * Np; idx += stride) {
    int n = idx % Np, cell = idx / Np;
    int h = n >> 2, gg = n & 3;
    g_bias[cell][n] = cell ? (bih1[gg * Hd + h] + bhh1[gg * Hd + h])
                           : (bih0[gg * Hd + h] + bhh0[gg * Hd + h]);
  }
  for (int idx = g0; idx < Bx * Kp; idx += stride) {
    int k = idx % Kp, m = idx / Kp;
    float v = (k < Hd) ? z[m * Hd + k] : 0.f;
    __nv_bfloat16 hi = __float2bfloat16(v);
    g_zHi[idx] = hi;
    g_zLo[idx] = __float2bfloat16(v - __bfloat162float(hi));
    __nv_bfloat16 zz = __float2bfloat16(0.f);
    g_hHi[0][0][idx] = zz; g_hLo[0][0][idx] = zz;
    g_hHi[0][1][idx] = zz; g_hLo[0][1][idx] = zz;
    g_hHi[1][0][idx] = zz; g_hLo[1][0][idx] = zz;
    g_hHi[1][1][idx] = zz; g_hLo[1][1][idx] = zz;
  }
  for (int idx = g0; idx < Hd * Bx; idx += stride) {
    g_c[0][idx] = 0.f;
    g_c[1][idx] = 0.f;
  }
}

#if !LSTM_TC
// ---- fallback epilogue: direct global writes (i,f,g,o interleaved) ------
__device__ __forceinline__ void cell_cols(const uint32_t* r, int nh, int cb,
                                          int n0, int m, const float* bsm,
                                          float* __restrict__ C,
                                          __nv_bfloat16* __restrict__ HoHi,
                                          __nv_bfloat16* __restrict__ HoLo,
                                          float* __restrict__ Y, int t) {
  for (int j = 0; j < nh; ++j) {
    int col = cb + j * 4;
    int hg = (n0 + col) >> 2;
    float vi = __uint_as_float(r[j * 4 + 0]) + bsm[col + 0];
    float vf = __uint_as_float(r[j * 4 + 1]) + bsm[col + 1];
    float vg = __uint_as_float(r[j * 4 + 2]) + bsm[col + 2];
    float vo = __uint_as_float(r[j * 4 + 3]) + bsm[col + 3];
    float i_ = sigmoid_f(vi);
    float f_ = sigmoid_f(vf);
    float g_ = tanh_f(vg);
    float o_ = sigmoid_f(vo);
    size_t ci = (size_t)hg * Bx + m;
    float c = f_ * C[ci] + i_ * g_;
    float h = o_ * tanh_f(c);
    C[ci] = c;
    __nv_bfloat16 hi = __float2bfloat16(h);
    HoHi[(size_t)m * Kp + hg] = hi;
    HoLo[(size_t)m * Kp + hg] = __float2bfloat16(h - __bfloat162float(hi));
    if (Y) Y[(size_t)m * (Tn * Hd) + (size_t)t * Hd + hg] = h;
  }
}
#endif

// ---- main fused GEMM + LSTM-cell kernel ---------------------------------
__global__ __launch_bounds__(256)
void lstm_tc_kernel(const __nv_bfloat16* __restrict__ Xhi,
                    const __nv_bfloat16* __restrict__ Xlo,
                    const __nv_bfloat16* __restrict__ Rhi,
                    const __nv_bfloat16* __restrict__ Rlo,
                    const __nv_bfloat16* __restrict__ WihHi,
                    const __nv_bfloat16* __restrict__ WihLo,
                    const __nv_bfloat16* __restrict__ WhhHi,
                    const __nv_bfloat16* __restrict__ WhhLo,
                    const float* __restrict__ bias, float* __restrict__ C,
                    __nv_bfloat16* __restrict__ HoHi,
                    __nv_bfloat16* __restrict__ HoLo, float* __restrict__ Y,
                    int t) {
  extern __shared__ __align__(1024) char smem[];
  const uint32_t sbase = (uint32_t)__cvta_generic_to_shared(smem);
  const int tid = threadIdx.x;
  const int wid = tid >> 5, lid = tid & 31;
  const int m0 = blockIdx.x * BM;
  const int n0 = blockIdx.y * BN;

#if LSTM_TC
  if (wid == 0) {
    asm volatile(
        "tcgen05.alloc.cta_group::1.sync.aligned.shared::cta.b32 [%0], %1;"
        :: "r"(sbase + SM_TMEM), "r"(256u) : "memory");
  }
  if (tid == 0) {
    asm volatile("mbarrier.init.shared.b64 [%0], 1;"
                 :: "r"(sbase + SM_MBAR) : "memory");
    asm volatile("mbarrier.init.shared.b64 [%0], 1;"
                 :: "r"(sbase + SM_MBAR + 8) : "memory");
  }
#else
  // Fallback: thread owns row tid>>1, cols (tid&1)*120 .. +119 (local mem).
  float facc[120];
  for (int i = 0; i < 120; ++i) facc[i] = 0.f;
  const int f_row = tid >> 1;
  const int f_ch  = tid & 1;
#endif
  if (tid < BN) {
    ((float*)(smem + SM_BIAS))[tid] = bias[n0 + tid];
  }
  __syncthreads();

#if LSTM_TC
  uint32_t tmem_base;
  asm volatile("ld.shared.b32 %0, [%1];"
               : "=r"(tmem_base) : "r"(sbase + SM_TMEM));
  const uint32_t dD = tmem_base;  // D in cols [0,240)
#endif

  const __nv_bfloat16* Ahis[2] = {Xhi, Rhi};
  const __nv_bfloat16* Alos[2] = {Xlo, Rlo};
  const __nv_bfloat16* Bhis[2] = {WihHi, WhhHi};
  const __nv_bfloat16* Blos[2] = {WihLo, WhhLo};

  #pragma unroll 1
  for (int it = 0; it < 2 * NKT; ++it) {
    const int ph = (it >= NKT) ? 1 : 0;
    const int k0 = (it - ph * NKT) * BK;
    const int buf = it & 1;
    const char* sm_st = smem + SM_STAGE0 + buf * STAGE_SZ;
#if LSTM_TC
    if (it >= 2) mbar_wait(sbase + SM_MBAR + 8 * buf, ((it - 2) >> 1) & 1);
#endif
    // A tiles: 128 rows x 128B (hi & lo)
    {
      const __nv_bfloat16* Ahi = Ahis[ph];
      const __nv_bfloat16* Alo = Alos[ph];
      for (int e = tid; e < BM * 8; e += 256) {
        int r = e >> 3, u = e & 7;
        const char* sh = (const char*)(Ahi + (size_t)(m0 + r) * Kp + k0);
        const char* sl = (const char*)(Alo + (size_t)(m0 + r) * Kp + k0);
        uint32_t off = SW128(r * 128 + u * 16);
        *(uint4*)(sm_st + ST_A_HI + off) = *(const uint4*)(sh + u * 16);
        *(uint4*)(sm_st + ST_A_LO + off) = *(const uint4*)(sl + u * 16);
      }
    }
    // B tiles: 240 rows x 128B (hi & lo)
    {
      const __nv_bfloat16* Bh = Bhis[ph];
      const __nv_bfloat16* Bl = Blos[ph];
      for (int e = tid; e < BN * 8; e += 256) {
        int r = e >> 3, u = e & 7;
        const char* sh = (const char*)(Bh + (size_t)(n0 + r) * Kp + k0);
        const char* sl = (const char*)(Bl + (size_t)(n0 + r) * Kp + k0);
        uint32_t off = SW128(r * 128 + u * 16);
        *(uint4*)(sm_st + ST_B_HI + off) = *(const uint4*)(sh + u * 16);
        *(uint4*)(sm_st + ST_B_LO + off) = *(const uint4*)(sl + u * 16);
      }
    }
    __syncthreads();
#if LSTM_TC
    if (tid == 0) {
      asm volatile("fence.proxy.async.shared::cta;" ::: "memory");
      const uint32_t stb = sbase + SM_STAGE0 + buf * STAGE_SZ;
      unsigned long long dAh = DESC_BASE | (((stb + ST_A_HI) >> 4) & 0x3FFF);
      unsigned long long dAl = DESC_BASE | (((stb + ST_A_LO) >> 4) & 0x3FFF);
      unsigned long long dBh = DESC_BASE | (((stb + ST_B_HI) >> 4) & 0x3FFF);
      unsigned long long dBl = DESC_BASE | (((stb + ST_B_LO) >> 4) & 0x3FFF);
      #pragma unroll
      for (int k16 = 0; k16 < 4; ++k16) {
        unsigned long long off = k16 * 2;  // 32B in 16B units
        uint32_t en0 = !(it == 0 && k16 == 0);
        #pragma unroll
        for (int half = 0; half < 2; ++half) {
          unsigned long long bo = off + half * 960;  // +120 rows = 15360B/16
          uint32_t dDh = dD + half * 120;
          mma_f16_ss(dDh, dAh + off, dBh + bo, en0);
          mma_f16_ss(dDh, dAh + off, dBl + bo, 1);
          mma_f16_ss(dDh, dAl + off, dBh + bo, 1);
        }
      }
      asm volatile(
          "tcgen05.commit.cta_group::1.mbarrier::arrive::one.shared::cluster.b64 [%0];"
          :: "r"(sbase + SM_MBAR + 8 * buf) : "memory");
    }
    // no wait here — next iteration loads the other stage while MMA runs
#else
    // Fallback SIMT accumulate from the same swizzled smem tiles.
    for (int k = 0; k < BK; ++k) {
      uint32_t ao = SW128(f_row * 128 + k * 2);
      float a = __bfloat162float(*(const __nv_bfloat16*)(sm_st + ST_A_HI + ao)) +
                __bfloat162float(*(const __nv_bfloat16*)(sm_st + ST_A_LO + ao));
      for (int c = 0; c < 120; ++c) {
        int bn = f_ch * 120 + c;
        uint32_t bo = SW128(bn * 128 + k * 2);
        float b = __bfloat162float(*(const __nv_bfloat16*)(sm_st + ST_B_HI + bo)) +
                  __bfloat162float(*(const __nv_bfloat16*)(sm_st + ST_B_LO + bo));
        facc[c] = fmaf(a, b, facc[c]);
      }
    }
#endif
  }

#if LSTM_TC
  // Wait for the final commit (covers ALL issued MMAs).
  mbar_wait(sbase + SM_MBAR + 8, ((2 * NKT - 1) >> 1) & 1);
  asm volatile("tcgen05.fence::after_thread_sync;" ::: "memory");

  // ---- fused LSTM epilogue: compute into smem staging (stage 0 is dead) --
  __nv_bfloat16* hst_hi = (__nv_bfloat16*)(smem + EP_HHI);
  __nv_bfloat16* hst_lo = (__nv_bfloat16*)(smem + EP_HLO);
  float* yst = (float*)(smem + EP_Y);
  if (wid < 4) {
    const int ml = wid * 32 + lid;       // local m row 0..127
    const int m = m0 + ml;
    const int hg0 = n0 >> 2;
    const float* bsm = (const float*)(smem + SM_BIAS);
    uint32_t r[32];
    #pragma unroll 1
    for (int cbi = 0; cbi < 8; ++cbi) {
      const int cb = cbi * 32;
      const int nh = (cbi < 7) ? 8 : 4;
      if (cbi < 7) {
        ldtm_x32(r, dD + cb);
      } else {
        ldtm_x16(r, dD + cb);
      }
      asm volatile("tcgen05.wait::ld.sync.aligned;" ::: "memory");
      #pragma unroll
      for (int j = 0; j < 8; ++j) {
        if (j >= nh) break;
        int col = cb + j * 4;
        int hgl = col >> 2;
        float vi = __uint_as_float(r[j * 4 + 0]) + bsm[col + 0];
        float vf = __uint_as_float(r[j * 4 + 1]) + bsm[col + 1];
        float vg = __uint_as_float(r[j * 4 + 2]) + bsm[col + 2];
        float vo = __uint_as_float(r[j * 4 + 3]) + bsm[col + 3];
        float i_ = sigmoid_f(vi);
        float f_ = sigmoid_f(vf);
        float g_ = tanh_f(vg);
        float o_ = sigmoid_f(vo);
        size_t ci = (size_t)(hg0 + hgl) * Bx + m;
        float c = f_ * C[ci] + i_ * g_;
        float h = o_ * tanh_f(c);
        C[ci] = c;
        __nv_bfloat16 hi = __float2bfloat16(h);
        hst_hi[ml * NH + hgl] = hi;
        hst_lo[ml * NH + hgl] = __float2bfloat16(h - __bfloat162float(hi));
        yst[ml * NH + hgl] = h;
      }
    }
  }
  __syncthreads();
  // Coalesced copy-out of the staged h (and y) tile.
  {
    const int hg0 = n0 >> 2;
    for (int e = tid; e < BM * NH; e += 256) {
      int m = e / NH, j = e - (e / NH) * NH;
      size_t ho = (size_t)(m0 + m) * Kp + hg0 + j;
      HoHi[ho] = hst_hi[e];
      HoLo[ho] = hst_lo[e];
    }
    if (Y) {
      for (int e = tid; e < BM * NH; e += 256) {
        int m = e / NH, j = e - (e / NH) * NH;
        Y[(size_t)(m0 + m) * (Tn * Hd) + (size_t)t * Hd + hg0 + j] = yst[e];
      }
    }
  }
  __syncthreads();
  if (tid == 0) {
    asm volatile("mbarrier.inval.shared.b64 [%0];"
                 :: "r"(sbase + SM_MBAR) : "memory");
    asm volatile("mbarrier.inval.shared.b64 [%0];"
                 :: "r"(sbase + SM_MBAR + 8) : "memory");
  }
  if (wid == 0) {
    asm volatile("tcgen05.relinquish_alloc_permit.cta_group::1.sync.aligned;");
    asm volatile("tcgen05.dealloc.cta_group::1.sync.aligned.b32 %0, %1;"
                 :: "r"(tmem_base), "r"(256u));
  }
#else
  {
    const float* bsm = (const float*)(smem + SM_BIAS);
    cell_cols((const uint32_t*)facc, 30, f_ch * 120, n0, m0 + f_row, bsm, C,
              HoHi, HoLo, Y, t);
  }
  (void)wid; (void)lid;
#endif
}

// ---- host side ----------------------------------------------------------
extern "C" void kernel_launch(void* const* d_in, const int* in_sizes, int n_in,
                              void* d_out, int out_size) {
  const float* z    = (const float*)d_in[0];
  const float* Wih0 = (const float*)d_in[1];
  const float* Whh0 = (const float*)d_in[2];
  const float* bih0 = (const float*)d_in[3];
  const float* bhh0 = (const float*)d_in[4];
  const float* Wih1 = (const float*)d_in[5];
  const float* Whh1 = (const float*)d_in[6];
  const float* bih1 = (const float*)d_in[7];
  const float* bhh1 = (const float*)d_in[8];
  float* out = (float*)d_out;

  cudaFuncSetAttribute(lstm_tc_kernel,
                       cudaFuncAttributeMaxDynamicSharedMemorySize, SM_TOTAL);

  void* p;
  cudaGetSymbolAddress(&p, g_WHi);  __nv_bfloat16* wHi = (__nv_bfloat16*)p;
  cudaGetSymbolAddress(&p, g_WLo);  __nv_bfloat16* wLo = (__nv_bfloat16*)p;
  cudaGetSymbolAddress(&p, g_bias); float* bias = (float*)p;
  cudaGetSymbolAddress(&p, g_zHi);  __nv_bfloat16* zHi = (__nv_bfloat16*)p;
  cudaGetSymbolAddress(&p, g_zLo);  __nv_bfloat16* zLo = (__nv_bfloat16*)p;
  cudaGetSymbolAddress(&p, g_hHi);  __nv_bfloat16* hHi = (__nv_bfloat16*)p;
  cudaGetSymbolAddress(&p, g_hLo);  __nv_bfloat16* hLo = (__nv_bfloat16*)p;
  cudaGetSymbolAddress(&p, g_c);    float* cst = (float*)p;

  const size_t WS = (size_t)Np * Kp;   // one weight matrix
  const size_t AS = (size_t)Bx * Kp;   // one activation buffer
  const size_t CS = (size_t)Hd * Bx;

  prep_kernel<<<1024, 256>>>(z, Wih0, Whh0, bih0, bhh0, Wih1, Whh1, bih1, bhh1);

  dim3 grid(NMT, NNT);  // 32 x 5
  for (int t = 0; t < Tn; ++t) {
    int cur = t & 1, nxt = cur ^ 1;
    // layer-0 input: z at t=0, else fed-back h1(t-1)
    const __nv_bfloat16* x0hi = (t == 0) ? zHi : hHi + (2 + cur) * AS;
    const __nv_bfloat16* x0lo = (t == 0) ? zLo : hLo + (2 + cur) * AS;
    lstm_tc_kernel<<<grid, 256, SM_TOTAL>>>(
        x0hi, x0lo, hHi + cur * AS, hLo + cur * AS,
        wHi + 0 * WS, wLo + 0 * WS, wHi + 1 * WS, wLo + 1 * WS,
        bias, cst, hHi + nxt * AS, hLo + nxt * AS, nullptr, t);
    lstm_tc_kernel<<<grid, 256, SM_TOTAL>>>(
        hHi + nxt * AS, hLo + nxt * AS, hHi + (2 + cur) * AS, hLo + (2 + cur) * AS,
        wHi + 2 * WS, wLo + 2 * WS, wHi + 3 * WS, wLo + 3 * WS,
        bias + Np, cst + CS, hHi + (2 + nxt) * AS, hLo + (2 + nxt) * AS, out, t);
  }
}

// round 11
// speedup vs baseline: 2.0870x; 2.0870x over previous
#include <cuda_runtime.h>
#include <cuda_bf16.h>
#include <cstdint>

// 2-layer LSTM, B=4096, H=300, T=64. tcgen05 bf16-split MMA (hi*hi+hi*lo+lo*hi),
// D in TMEM fp32. All operands pre-tiled & SW128-pre-swizzled in GMEM so each
// pipeline stage is filled by 4 cp.async.bulk copies issued by ONE thread.
// Warp 0 orchestrates a 3-stage TMA->MMA pipeline (no __syncthreads in loop);
// warps 0-3 do the fused LSTM epilogue from TMEM at the end.

#if defined(__CUDA_ARCH_FEAT_SM103_ALL) || defined(__CUDA_ARCH_FEAT_SM100_ALL) || \
    defined(__CUDA_ARCH_FEAT_SM101_ALL) ||                                        \
    (defined(__CUDA_ARCH_FAMILY_SPECIFIC__) && (__CUDA_ARCH_FAMILY_SPECIFIC__ >= 1000))
#define LSTM_TC 1
#else
#define LSTM_TC 0
#endif

#define SW128(o) ((o) ^ (((o) >> 3) & 0x70))

namespace {
constexpr int Bx = 4096, Hd = 300, Tn = 64;
constexpr int Kp = 320;             // padded K per phase (300 -> 5*64)
constexpr int Np = 1200;            // 4*Hd, gate-interleaved (col n = 4*h+gate)
constexpr int BM = 128, BN = 120, BK = 64;
constexpr int NH = BN / 4;          // 30 h-groups per CTA
constexpr int NKT = Kp / BK;        // 5 k-tiles per phase
constexpr int NIT = 2 * NKT;        // 10 pipeline iterations
constexpr int NMT = Bx / BM;        // 32
constexpr int NNT = Np / BN;        // 10
// tile byte sizes (SW128-swizzled, contiguous in gmem)
constexpr int A_TILE = BM * 128;    // 16384
constexpr int B_TILE = BN * 128;    // 15360
constexpr unsigned IDESC = (1u << 4) | (1u << 7) | (1u << 10) |
                           ((BN / 8) << 17) | ((BM / 16) << 24);
constexpr unsigned long long DESC_BASE =  // SW128, Blackwell, SBO=64, LBO=1
    (2ull << 61) | (1ull << 46) | (64ull << 32) | (1ull << 16);
// smem layout
constexpr int SM_TMEM = 0;
constexpr int SM_FULL = 8;          // 3 mbarriers (TMA complete): 8,16,24
constexpr int SM_DONE = 32;         // 3 mbarriers (MMA commit):   32,40,48
constexpr int SM_BIAS = 64;         // 120 floats
constexpr int ST_A_HI = 0;
constexpr int ST_A_LO = A_TILE;                 // 16384
constexpr int ST_B_HI = 2 * A_TILE;             // 32768
constexpr int ST_B_LO = 2 * A_TILE + B_TILE;    // 48128
constexpr int STAGE_SZ = 2 * A_TILE + 2 * B_TILE;  // 63488 (62 KiB, 1024-mult)
constexpr int SM_STAGE0 = 1024;
constexpr int SM_TOTAL = SM_STAGE0 + 3 * STAGE_SZ;  // 191488
}

// ---- persistent device state (all tiled + swizzled) ---------------------
// weights: per matrix [nt(10)][kt(5)] tiles of B_TILE bytes
__device__ __align__(1024) __nv_bfloat16 g_WHi[4][Np * Kp];  // ih0,hh0,ih1,hh1
__device__ __align__(1024) __nv_bfloat16 g_WLo[4][Np * Kp];
// activations: buffers 0=z, 1/2=h0 ping-pong, 3/4=h1 ping-pong;
// per buffer [mt(32)][kt(5)] tiles of A_TILE bytes
__device__ __align__(1024) __nv_bfloat16 g_actHi[5][Bx * Kp];
__device__ __align__(1024) __nv_bfloat16 g_actLo[5][Bx * Kp];
__device__ float g_bias[2][Np];
__device__ float g_c[2][Hd * Bx];   // [cell][hg*Bx + m] (coalesced per warp)

// ---- helpers ------------------------------------------------------------
__device__ __forceinline__ float sigmoid_f(float v) {
  return __fdividef(1.0f, 1.0f + __expf(-v));
}
__device__ __forceinline__ float tanh_f(float v) {
  return 2.0f * __fdividef(1.0f, 1.0f + __expf(-2.0f * v)) - 1.0f;
}

#if LSTM_TC
__device__ __forceinline__ void mma_f16_ss(uint32_t d, unsigned long long da,
                                           unsigned long long db, uint32_t en) {
  asm volatile(
      "{\n\t.reg .pred p;\n\tsetp.ne.u32 p, %4, 0;\n\t"
      "tcgen05.mma.cta_group::1.kind::f16 [%0], %1, %2, %3, {%5, %5, %5, %5}, p;\n\t}"
      :: "r"(d), "l"(da), "l"(db), "r"(IDESC), "r"(en), "r"(0u) : "memory");
}
__device__ __forceinline__ void mbar_wait(uint32_t mbar, uint32_t parity) {
  uint32_t done;
  asm volatile(
      "{\n\t.reg .pred p;\n\t"
      "mbarrier.try_wait.parity.acquire.cta.shared::cta.b64 p, [%1], %2;\n\t"
      "selp.b32 %0, 1, 0, p;\n\t}"
      : "=r"(done) : "r"(mbar), "r"(parity) : "memory");
  if (!done) {
    asm volatile(
        "{\n\t.reg .pred P1;\n\t"
        "W_%=:\n\t"
        "mbarrier.try_wait.parity.acquire.cta.shared::cta.b64 P1, [%0], %1, 0x989680;\n\t"
        "@P1 bra.uni D_%=;\n\t"
        "bra.uni W_%=;\n\t"
        "D_%=:\n\t}"
        :: "r"(mbar), "r"(parity) : "memory");
  }
}
__device__ __forceinline__ void bulk_cp(uint32_t dst, const void* src,
                                        uint32_t bytes, uint32_t mbar) {
  asm volatile(
      "cp.async.bulk.shared::cta.global.mbarrier::complete_tx::bytes "
      "[%0], [%1], %2, [%3];"
      :: "r"(dst), "l"(src), "r"(bytes), "r"(mbar) : "memory");
}
__device__ __forceinline__ void ldtm_x32(uint32_t* r, uint32_t a) {
  asm volatile(
      "tcgen05.ld.sync.aligned.32x32b.x32.b32 "
      "{%0,%1,%2,%3,%4,%5,%6,%7,%8,%9,%10,%11,%12,%13,%14,%15,"
      "%16,%17,%18,%19,%20,%21,%22,%23,%24,%25,%26,%27,%28,%29,%30,%31}, [%32];"
      : "=r"(r[0]), "=r"(r[1]), "=r"(r[2]), "=r"(r[3]), "=r"(r[4]), "=r"(r[5]),
        "=r"(r[6]), "=r"(r[7]), "=r"(r[8]), "=r"(r[9]), "=r"(r[10]), "=r"(r[11]),
        "=r"(r[12]), "=r"(r[13]), "=r"(r[14]), "=r"(r[15]), "=r"(r[16]),
        "=r"(r[17]), "=r"(r[18]), "=r"(r[19]), "=r"(r[20]), "=r"(r[21]),
        "=r"(r[22]), "=r"(r[23]), "=r"(r[24]), "=r"(r[25]), "=r"(r[26]),
        "=r"(r[27]), "=r"(r[28]), "=r"(r[29]), "=r"(r[30]), "=r"(r[31])
      : "r"(a));
}
__device__ __forceinline__ void ldtm_x16(uint32_t* r, uint32_t a) {
  asm volatile(
      "tcgen05.ld.sync.aligned.32x32b.x16.b32 "
      "{%0,%1,%2,%3,%4,%5,%6,%7,%8,%9,%10,%11,%12,%13,%14,%15}, [%16];"
      : "=r"(r[0]), "=r"(r[1]), "=r"(r[2]), "=r"(r[3]), "=r"(r[4]), "=r"(r[5]),
        "=r"(r[6]), "=r"(r[7]), "=r"(r[8]), "=r"(r[9]), "=r"(r[10]), "=r"(r[11]),
        "=r"(r[12]), "=r"(r[13]), "=r"(r[14]), "=r"(r[15])
      : "r"(a));
}
__device__ __forceinline__ void ldtm_x8(uint32_t* r, uint32_t a) {
  asm volatile(
      "tcgen05.ld.sync.aligned.32x32b.x8.b32 {%0,%1,%2,%3,%4,%5,%6,%7}, [%8];"
      : "=r"(r[0]), "=r"(r[1]), "=r"(r[2]), "=r"(r[3]), "=r"(r[4]), "=r"(r[5]),
        "=r"(r[6]), "=r"(r[7])
      : "r"(a));
}
#endif  // LSTM_TC

// ---- prep: split/tile/swizzle weights & z; biases; zero state -----------
__global__ void prep_kernel(const float* __restrict__ z,
                            const float* __restrict__ Wih0,
                            const float* __restrict__ Whh0,
                            const float* __restrict__ bih0,
                            const float* __restrict__ bhh0,
                            const float* __restrict__ Wih1,
                            const float* __restrict__ Whh1,
                            const float* __restrict__ bih1,
                            const float* __restrict__ bhh1) {
  const int stride = gridDim.x * blockDim.x;
  const int g0 = blockIdx.x * blockDim.x + threadIdx.x;
  const float* Ws[4] = {Wih0, Whh0, Wih1, Whh1};
  char* wHiB = (char*)g_WHi;
  char* wLoB = (char*)g_WLo;
  for (int idx = g0; idx < 4 * Np * Kp; idx += stride) {
    int k = idx % Kp;
    int rr = idx / Kp;
    int n = rr % Np;
    int mi = rr / Np;
    int h = n >> 2, gg = n & 3;
    float w = (k < Hd) ? Ws[mi][(gg * Hd + h) * Hd + k] : 0.f;
    __nv_bfloat16 hi = __float2bfloat16(w);
    int nt = n / BN, r = n % BN, kt = k / BK, cc = k % BK;
    size_t off = (size_t)mi * (Np * Kp * 2) + (size_t)(nt * NKT + kt) * B_TILE +
                 SW128(r * 128 + cc * 2);
    *(__nv_bfloat16*)(wHiB + off) = hi;
    *(__nv_bfloat16*)(wLoB + off) = __float2bfloat16(w - __bfloat162float(hi));
  }
  for (int idx = g0; idx < 2 * Np; idx += stride) {
    int n = idx % Np, cell = idx / Np;
    int h = n >> 2, gg = n & 3;
    g_bias[cell][n] = cell ? (bih1[gg * Hd + h] + bhh1[gg * Hd + h])
                           : (bih0[gg * Hd + h] + bhh0[gg * Hd + h]);
  }
  char* aHiB = (char*)g_actHi;
  char* aLoB = (char*)g_actLo;
  for (int idx = g0; idx < Bx * Kp; idx += stride) {
    int k = idx % Kp, m = idx / Kp;
    float v = (k < Hd) ? z[m * Hd + k] : 0.f;
    __nv_bfloat16 hi = __float2bfloat16(v);
    int mt = m / BM, r = m % BM, kt = k / BK, cc = k % BK;
    size_t off = (size_t)(mt * NKT + kt) * A_TILE + SW128(r * 128 + cc * 2);
    *(__nv_bfloat16*)(aHiB + off) = hi;
    *(__nv_bfloat16*)(aLoB + off) = __float2bfloat16(v - __bfloat162float(hi));
  }
  // zero h buffers (1..4) vectorized; zero c
  uint4* zh = (uint4*)(g_actHi[1]);
  uint4* zl = (uint4*)(g_actLo[1]);
  const int nq = 4 * Bx * Kp * 2 / 16;
  uint4 zz = {0u, 0u, 0u, 0u};
  for (int idx = g0; idx < nq; idx += stride) { zh[idx] = zz; zl[idx] = zz; }
  for (int idx = g0; idx < Hd * Bx; idx += stride) {
    g_c[0][idx] = 0.f;
    g_c[1][idx] = 0.f;
  }
}

// ---- main fused GEMM + LSTM-cell kernel ---------------------------------
__global__ __launch_bounds__(256)
void lstm_tc_kernel(const __nv_bfloat16* __restrict__ Xhi,   // tiled act
                    const __nv_bfloat16* __restrict__ Xlo,
                    const __nv_bfloat16* __restrict__ Rhi,
                    const __nv_bfloat16* __restrict__ Rlo,
                    const __nv_bfloat16* __restrict__ WihHi,  // tiled weights
                    const __nv_bfloat16* __restrict__ WihLo,
                    const __nv_bfloat16* __restrict__ WhhHi,
                    const __nv_bfloat16* __restrict__ WhhLo,
                    const float* __restrict__ bias, float* __restrict__ C,
                    __nv_bfloat16* __restrict__ HoHi,         // tiled act out
                    __nv_bfloat16* __restrict__ HoLo, float* __restrict__ Y,
                    int t) {
  extern __shared__ __align__(1024) char smem[];
  const uint32_t sbase = (uint32_t)__cvta_generic_to_shared(smem);
  const int tid = threadIdx.x;
  const int wid = tid >> 5, lid = tid & 31;
  const int mt = blockIdx.x;
  const int nt = blockIdx.y;
  const int m0 = mt * BM;

#if LSTM_TC
  if (wid == 0) {
    asm volatile(
        "tcgen05.alloc.cta_group::1.sync.aligned.shared::cta.b32 [%0], %1;"
        :: "r"(sbase + SM_TMEM), "r"(128u) : "memory");
  }
  if (tid == 0) {
    #pragma unroll
    for (int s = 0; s < 3; ++s) {
      asm volatile("mbarrier.init.shared.b64 [%0], 1;"
                   :: "r"(sbase + SM_FULL + 8 * s) : "memory");
      asm volatile("mbarrier.init.shared.b64 [%0], 1;"
                   :: "r"(sbase + SM_DONE + 8 * s) : "memory");
    }
  }
#endif
  if (tid < BN) {
    ((float*)(smem + SM_BIAS))[tid] = bias[nt * BN + tid];
  }
  __syncthreads();

#if LSTM_TC
  uint32_t tmem_base;
  asm volatile("ld.shared.b32 %0, [%1];"
               : "=r"(tmem_base) : "r"(sbase + SM_TMEM));
  const uint32_t dD = tmem_base;  // D cols [0,120)

  // ---- single-warp 3-stage TMA->MMA pipeline ----------------------------
  if (wid == 0) {
    const char* Asrc[2][2] = {{(const char*)Xhi, (const char*)Xlo},
                              {(const char*)Rhi, (const char*)Rlo}};
    const char* Bsrc[2][2] = {{(const char*)WihHi, (const char*)WihLo},
                              {(const char*)WhhHi, (const char*)WhhLo}};
    const bool l0 = (lid == 0);

    auto issue_load = [&](int it2) {
      const int phl = (it2 >= NKT) ? 1 : 0;
      const int ktt = it2 - phl * NKT;
      const int s = it2 % 3;
      const uint32_t stb = sbase + SM_STAGE0 + s * STAGE_SZ;
      const uint32_t mb = sbase + SM_FULL + 8 * s;
      if (l0) {
        asm volatile("mbarrier.arrive.expect_tx.shared.b64 _, [%0], %1;"
                     :: "r"(mb), "r"((uint32_t)STAGE_SZ) : "memory");
        const size_t aoff = (size_t)(mt * NKT + ktt) * A_TILE;
        const size_t boff = (size_t)(nt * NKT + ktt) * B_TILE;
        bulk_cp(stb + ST_A_HI, Asrc[phl][0] + aoff, A_TILE, mb);
        bulk_cp(stb + ST_A_LO, Asrc[phl][1] + aoff, A_TILE, mb);
        bulk_cp(stb + ST_B_HI, Bsrc[phl][0] + boff, B_TILE, mb);
        bulk_cp(stb + ST_B_LO, Bsrc[phl][1] + boff, B_TILE, mb);
      }
    };

    issue_load(0);
    issue_load(1);
    #pragma unroll 1
    for (int j = 0; j < NIT; ++j) {
      const int s = j % 3;
      mbar_wait(sbase + SM_FULL + 8 * s, (uint32_t)((j / 3) & 1));
      if (l0) {
        const uint32_t stb = sbase + SM_STAGE0 + s * STAGE_SZ;
        unsigned long long dAh = DESC_BASE | (((stb + ST_A_HI) >> 4) & 0x3FFF);
        unsigned long long dAl = DESC_BASE | (((stb + ST_A_LO) >> 4) & 0x3FFF);
        unsigned long long dBh = DESC_BASE | (((stb + ST_B_HI) >> 4) & 0x3FFF);
        unsigned long long dBl = DESC_BASE | (((stb + ST_B_LO) >> 4) & 0x3FFF);
        #pragma unroll
        for (int k16 = 0; k16 < 4; ++k16) {
          unsigned long long off = k16 * 2;  // 32B in 16B units
          mma_f16_ss(dD, dAh + off, dBh + off, !(j == 0 && k16 == 0));
          mma_f16_ss(dD, dAh + off, dBl + off, 1);
          mma_f16_ss(dD, dAl + off, dBh + off, 1);
        }
        asm volatile(
            "tcgen05.commit.cta_group::1.mbarrier::arrive::one.shared::cluster.b64 [%0];"
            :: "r"(sbase + SM_DONE + 8 * s) : "memory");
      }
      if (j + 2 < NIT) {
        if (j >= 1) {
          // recycle stage (j-1)%3: freed once MMA(j-1) committed
          mbar_wait(sbase + SM_DONE + 8 * ((j - 1) % 3),
                    (uint32_t)(((j - 1) / 3) & 1));
        }
        issue_load(j + 2);
      }
    }
    // final commit (FIFO => all MMAs complete)
    mbar_wait(sbase + SM_DONE + 8 * ((NIT - 1) % 3),
              (uint32_t)(((NIT - 1) / 3) & 1));
  }
  __syncthreads();

  // ---- fused LSTM epilogue (warps 0-3 read TMEM subpartitions) ----------
  if (wid < 4) {
    asm volatile("tcgen05.fence::after_thread_sync;" ::: "memory");
    const int ml = wid * 32 + lid;   // local row
    const int m = m0 + ml;
    const int hg0 = nt * NH;
    const float* bsm = (const float*)(smem + SM_BIAS);
    char* hoHiB = (char*)HoHi;
    char* hoLoB = (char*)HoLo;
    uint32_t r[32];
    #pragma unroll 1
    for (int cbi = 0; cbi < 5; ++cbi) {
      const int cb = (cbi < 4) ? cbi * 32 : 112;
      const int nh = (cbi < 3) ? 8 : ((cbi == 3) ? 4 : 2);
      if (cbi < 3)      ldtm_x32(r, dD + cb);
      else if (cbi == 3) ldtm_x16(r, dD + cb);
      else               ldtm_x8(r, dD + cb);
      asm volatile("tcgen05.wait::ld.sync.aligned;" ::: "memory");
      #pragma unroll
      for (int j = 0; j < 8; ++j) {
        if (j >= nh) break;
        const int col = cb + j * 4;
        const int hg = hg0 + (col >> 2);
        float vi = __uint_as_float(r[j * 4 + 0]) + bsm[col + 0];
        float vf = __uint_as_float(r[j * 4 + 1]) + bsm[col + 1];
        float vg = __uint_as_float(r[j * 4 + 2]) + bsm[col + 2];
        float vo = __uint_as_float(r[j * 4 + 3]) + bsm[col + 3];
        float i_ = sigmoid_f(vi);
        float f_ = sigmoid_f(vf);
        float g_ = tanh_f(vg);
        float o_ = sigmoid_f(vo);
        size_t ci = (size_t)hg * Bx + m;
        float c = f_ * C[ci] + i_ * g_;
        float h = o_ * tanh_f(c);
        C[ci] = c;
        // write h into tiled+swizzled activation layout
        const int kt2 = hg >> 6, cc = hg & 63;
        size_t off = (size_t)(mt * NKT + kt2) * A_TILE + SW128(ml * 128 + cc * 2);
        __nv_bfloat16 hi = __float2bfloat16(h);
        *(__nv_bfloat16*)(hoHiB + off) = hi;
        *(__nv_bfloat16*)(hoLoB + off) =
            __float2bfloat16(h - __bfloat162float(hi));
        if (Y) Y[(size_t)m * (Tn * Hd) + (size_t)t * Hd + hg] = h;
      }
    }
  }
  __syncthreads();
  if (tid == 0) {
    #pragma unroll
    for (int s = 0; s < 3; ++s) {
      asm volatile("mbarrier.inval.shared.b64 [%0];"
                   :: "r"(sbase + SM_FULL + 8 * s) : "memory");
      asm volatile("mbarrier.inval.shared.b64 [%0];"
                   :: "r"(sbase + SM_DONE + 8 * s) : "memory");
    }
  }
  if (wid == 0) {
    asm volatile("tcgen05.relinquish_alloc_permit.cta_group::1.sync.aligned;");
    asm volatile("tcgen05.dealloc.cta_group::1.sync.aligned.b32 %0, %1;"
                 :: "r"(tmem_base), "r"(128u));
  }
#else
  // ---- SIMT fallback: read tiled global directly, accumulate fp32 -------
  float facc[NH * 2];
  for (int i = 0; i < NH * 2; ++i) facc[i] = 0.f;
  const int f_row = tid >> 1;
  const int f_ch = tid & 1;  // cols [f_ch*60, +60)
  const char* Asrc[2][2] = {{(const char*)Xhi, (const char*)Xlo},
                            {(const char*)Rhi, (const char*)Rlo}};
  const char* Bsrc[2][2] = {{(const char*)WihHi, (const char*)WihLo},
                            {(const char*)WhhHi, (const char*)WhhLo}};
  for (int it = 0; it < NIT; ++it) {
    int phl = (it >= NKT) ? 1 : 0;
    int ktt = it - phl * NKT;
    size_t at = (size_t)(mt * NKT + ktt) * A_TILE;
    size_t bt = (size_t)(nt * NKT + ktt) * B_TILE;
    for (int k = 0; k < BK; ++k) {
      uint32_t ao = SW128(f_row * 128 + k * 2);
      float a =
          __bfloat162float(*(const __nv_bfloat16*)(Asrc[phl][0] + at + ao)) +
          __bfloat162float(*(const __nv_bfloat16*)(Asrc[phl][1] + at + ao));
      for (int c = 0; c < 60; ++c) {
        int bn = f_ch * 60 + c;
        uint32_t bo = SW128(bn * 128 + k * 2);
        float b =
            __bfloat162float(*(const __nv_bfloat16*)(Bsrc[phl][0] + bt + bo)) +
            __bfloat162float(*(const __nv_bfloat16*)(Bsrc[phl][1] + bt + bo));
        facc[c] = fmaf(a, b, facc[c]);
      }
    }
  }
  {
    const float* bsm = (const float*)(smem + SM_BIAS);
    const int m = m0 + f_row;
    char* hoHiB = (char*)HoHi;
    char* hoLoB = (char*)HoLo;
    for (int jh = 0; jh < 15; ++jh) {
      int col = f_ch * 60 + jh * 4;
      int hg = nt * NH + (col >> 2);
      float i_ = sigmoid_f(facc[jh * 4 + 0] + bsm[col + 0]);
      float f_ = sigmoid_f(facc[jh * 4 + 1] + bsm[col + 1]);
      float g_ = tanh_f(facc[jh * 4 + 2] + bsm[col + 2]);
      float o_ = sigmoid_f(facc[jh * 4 + 3] + bsm[col + 3]);
      size_t ci = (size_t)hg * Bx + m;
      float c = f_ * C[ci] + i_ * g_;
      float h = o_ * tanh_f(c);
      C[ci] = c;
      const int kt2 = hg >> 6, cc = hg & 63;
      size_t off = (size_t)(mt * NKT + kt2) * A_TILE + SW128(f_row * 128 + cc * 2);
      __nv_bfloat16 hi = __float2bfloat16(h);
      *(__nv_bfloat16*)(hoHiB + off) = hi;
      *(__nv_bfloat16*)(hoLoB + off) = __float2bfloat16(h - __bfloat162float(hi));
      if (Y) Y[(size_t)m * (Tn * Hd) + (size_t)t * Hd + hg] = h;
    }
  }
  (void)wid; (void)lid;
#endif
}

// ---- host side ----------------------------------------------------------
extern "C" void kernel_launch(void* const* d_in, const int* in_sizes, int n_in,
                              void* d_out, int out_size) {
  const float* z    = (const float*)d_in[0];
  const float* Wih0 = (const float*)d_in[1];
  const float* Whh0 = (const float*)d_in[2];
  const float* bih0 = (const float*)d_in[3];
  const float* bhh0 = (const float*)d_in[4];
  const float* Wih1 = (const float*)d_in[5];
  const float* Whh1 = (const float*)d_in[6];
  const float* bih1 = (const float*)d_in[7];
  const float* bhh1 = (const float*)d_in[8];
  float* out = (float*)d_out;

  cudaFuncSetAttribute(lstm_tc_kernel,
                       cudaFuncAttributeMaxDynamicSharedMemorySize, SM_TOTAL);

  void* p;
  cudaGetSymbolAddress(&p, g_WHi);   __nv_bfloat16* wHi = (__nv_bfloat16*)p;
  cudaGetSymbolAddress(&p, g_WLo);   __nv_bfloat16* wLo = (__nv_bfloat16*)p;
  cudaGetSymbolAddress(&p, g_bias);  float* bias = (float*)p;
  cudaGetSymbolAddress(&p, g_actHi); __nv_bfloat16* aHi = (__nv_bfloat16*)p;
  cudaGetSymbolAddress(&p, g_actLo); __nv_bfloat16* aLo = (__nv_bfloat16*)p;
  cudaGetSymbolAddress(&p, g_c);     float* cst = (float*)p;

  const size_t WS = (size_t)Np * Kp;   // one weight matrix (elements)
  const size_t AS = (size_t)Bx * Kp;   // one activation buffer (elements)
  const size_t CS = (size_t)Hd * Bx;

  prep_kernel<<<1024, 256>>>(z, Wih0, Whh0, bih0, bhh0, Wih1, Whh1, bih1, bhh1);

  dim3 grid(NMT, NNT);  // 32 x 10
  for (int t = 0; t < Tn; ++t) {
    int cur = t & 1, nxt = cur ^ 1;
    // act buffer ids: 0=z, 1/2=h0 ping-pong, 3/4=h1 ping-pong
    const __nv_bfloat16* x0hi = (t == 0) ? aHi : aHi + (3 + cur) * AS;
    const __nv_bfloat16* x0lo = (t == 0) ? aLo : aLo + (3 + cur) * AS;
    lstm_tc_kernel<<<grid, 256, SM_TOTAL>>>(
        x0hi, x0lo, aHi + (1 + cur) * AS, aLo + (1 + cur) * AS,
        wHi + 0 * WS, wLo + 0 * WS, wHi + 1 * WS, wLo + 1 * WS,
        bias, cst, aHi + (1 + nxt) * AS, aLo + (1 + nxt) * AS, nullptr, t);
    lstm_tc_kernel<<<grid, 256, SM_TOTAL>>>(
        aHi + (1 + nxt) * AS, aLo + (1 + nxt) * AS,
        aHi + (3 + cur) * AS, aLo + (3 + cur) * AS,
        wHi + 2 * WS, wLo + 2 * WS, wHi + 3 * WS, wLo + 3 * WS,
        bias + Np, cst + CS, aHi + (3 + nxt) * AS, aLo + (3 + nxt) * AS, out, t);
  }
}

// round 14
// speedup vs baseline: 2.7540x; 1.3196x over previous
#include <cuda_runtime.h>
#include <cuda_bf16.h>
#include <cstdint>

// 2-layer LSTM, B=4096, H=300, T=64. tcgen05 bf16-split MMA (hi*hi+hi*lo+lo*hi),
// D in TMEM fp32. Operands pre-tiled & SW128-pre-swizzled in GMEM; each stage
// is filled by 4 cp.async.bulk copies from ONE thread. Warp 0 runs a 2-stage
// TMA->MMA pipeline; CTA tile M=128 x N=240 (two N=120 MMAs -> TMEM cols
// 0/120), grid 32x5=160 (~1 wave). Epilogue stages h/y in smem, copies out
// vectorized. NOTE: all SW128 descriptor bases MUST be 1024-aligned
// (SM_STAGE0=1024, STAGE_SZ/ST_* all multiples of 1024) — R12 broke this.

#if defined(__CUDA_ARCH_FEAT_SM103_ALL) || defined(__CUDA_ARCH_FEAT_SM100_ALL) || \
    defined(__CUDA_ARCH_FEAT_SM101_ALL) ||                                        \
    (defined(__CUDA_ARCH_FAMILY_SPECIFIC__) && (__CUDA_ARCH_FAMILY_SPECIFIC__ >= 1000))
#define LSTM_TC 1
#else
#define LSTM_TC 0
#endif

#define SW128(o) ((o) ^ (((o) >> 3) & 0x70))

namespace {
constexpr int Bx = 4096, Hd = 300, Tn = 64;
constexpr int Kp = 320;             // padded K per phase (300 -> 5*64)
constexpr int Np = 1200;            // 4*Hd, gate-interleaved (col n = 4*h+gate)
constexpr int BM = 128, BN = 240, BK = 64;
constexpr int NH = BN / 4;          // 60 h-groups per CTA
constexpr int NKT = Kp / BK;        // 5 k-tiles per phase
constexpr int NIT = 2 * NKT;        // 10 pipeline iterations
constexpr int NMT = Bx / BM;        // 32
constexpr int NNT = Np / BN;        // 5
// tile byte sizes (SW128-swizzled, contiguous in gmem)
constexpr int A_TILE = BM * 128;    // 16384
constexpr int B_TILE = BN * 128;    // 30720
constexpr unsigned IDESC = (1u << 4) | (1u << 7) | (1u << 10) |
                           ((120 / 8) << 17) | ((BM / 16) << 24);  // N=120/MMA
constexpr unsigned long long DESC_BASE =  // SW128, Blackwell, SBO=64, LBO=1
    (2ull << 61) | (1ull << 46) | (64ull << 32) | (1ull << 16);
// smem layout — bias ends exactly at 1024 so stage 0 is 1024-aligned.
constexpr int SM_TMEM = 0;
constexpr int SM_FULL = 8;          // 2 mbarriers (TMA complete): 8,16
constexpr int SM_DONE = 24;         // 2 mbarriers (MMA commit):   24,32
constexpr int SM_BIAS = 64;         // 240 floats -> [64, 1024)
constexpr int ST_A_HI = 0;
constexpr int ST_A_LO = A_TILE;                 // 16384
constexpr int ST_B_HI = 2 * A_TILE;             // 32768
constexpr int ST_B_LO = 2 * A_TILE + B_TILE;    // 63488
constexpr int STAGE_SZ = 2 * A_TILE + 2 * B_TILE;  // 94208 = 92*1024
constexpr int SM_STAGE0 = 1024;     // MUST be 1024-aligned for SW128 desc
constexpr int SM_TOTAL = SM_STAGE0 + 2 * STAGE_SZ;  // 189440
// epilogue staging (stage 0 is dead after mainloop)
constexpr int EP_HHI = SM_STAGE0;                  // bf16[128*60] = 15360
constexpr int EP_HLO = EP_HHI + BM * NH * 2;
constexpr int EP_Y   = EP_HLO + BM * NH * 2;       // float[128*60] = 30720
}

// ---- persistent device state (all tiled + swizzled) ---------------------
// weights: per matrix [nt(5)][kt(5)] tiles of B_TILE bytes
__device__ __align__(1024) __nv_bfloat16 g_WHi[4][Np * Kp];  // ih0,hh0,ih1,hh1
__device__ __align__(1024) __nv_bfloat16 g_WLo[4][Np * Kp];
// activations: buffers 0=z, 1/2=h0 ping-pong, 3/4=h1 ping-pong;
// per buffer [mt(32)][kt(5)] tiles of A_TILE bytes
__device__ __align__(1024) __nv_bfloat16 g_actHi[5][Bx * Kp];
__device__ __align__(1024) __nv_bfloat16 g_actLo[5][Bx * Kp];
__device__ float g_bias[2][Np];
__device__ float g_c[2][Hd * Bx];   // [cell][hg*Bx + m] (coalesced per warp)

// ---- helpers ------------------------------------------------------------
__device__ __forceinline__ float sigmoid_f(float v) {
  return __fdividef(1.0f, 1.0f + __expf(-v));
}
__device__ __forceinline__ float tanh_f(float v) {
  return 2.0f * __fdividef(1.0f, 1.0f + __expf(-2.0f * v)) - 1.0f;
}

#if LSTM_TC
__device__ __forceinline__ void mma_f16_ss(uint32_t d, unsigned long long da,
                                           unsigned long long db, uint32_t en) {
  asm volatile(
      "{\n\t.reg .pred p;\n\tsetp.ne.u32 p, %4, 0;\n\t"
      "tcgen05.mma.cta_group::1.kind::f16 [%0], %1, %2, %3, {%5, %5, %5, %5}, p;\n\t}"
      :: "r"(d), "l"(da), "l"(db), "r"(IDESC), "r"(en), "r"(0u) : "memory");
}
__device__ __forceinline__ void mbar_wait(uint32_t mbar, uint32_t parity) {
  uint32_t done;
  asm volatile(
      "{\n\t.reg .pred p;\n\t"
      "mbarrier.try_wait.parity.acquire.cta.shared::cta.b64 p, [%1], %2;\n\t"
      "selp.b32 %0, 1, 0, p;\n\t}"
      : "=r"(done) : "r"(mbar), "r"(parity) : "memory");
  if (!done) {
    asm volatile(
        "{\n\t.reg .pred P1;\n\t"
        "W_%=:\n\t"
        "mbarrier.try_wait.parity.acquire.cta.shared::cta.b64 P1, [%0], %1, 0x989680;\n\t"
        "@P1 bra.uni D_%=;\n\t"
        "bra.uni W_%=;\n\t"
        "D_%=:\n\t}"
        :: "r"(mbar), "r"(parity) : "memory");
  }
}
__device__ __forceinline__ void bulk_cp(uint32_t dst, const void* src,
                                        uint32_t bytes, uint32_t mbar) {
  asm volatile(
      "cp.async.bulk.shared::cta.global.mbarrier::complete_tx::bytes "
      "[%0], [%1], %2, [%3];"
      :: "r"(dst), "l"(src), "r"(bytes), "r"(mbar) : "memory");
}
__device__ __forceinline__ void ldtm_x32(uint32_t* r, uint32_t a) {
  asm volatile(
      "tcgen05.ld.sync.aligned.32x32b.x32.b32 "
      "{%0,%1,%2,%3,%4,%5,%6,%7,%8,%9,%10,%11,%12,%13,%14,%15,"
      "%16,%17,%18,%19,%20,%21,%22,%23,%24,%25,%26,%27,%28,%29,%30,%31}, [%32];"
      : "=r"(r[0]), "=r"(r[1]), "=r"(r[2]), "=r"(r[3]), "=r"(r[4]), "=r"(r[5]),
        "=r"(r[6]), "=r"(r[7]), "=r"(r[8]), "=r"(r[9]), "=r"(r[10]), "=r"(r[11]),
        "=r"(r[12]), "=r"(r[13]), "=r"(r[14]), "=r"(r[15]), "=r"(r[16]),
        "=r"(r[17]), "=r"(r[18]), "=r"(r[19]), "=r"(r[20]), "=r"(r[21]),
        "=r"(r[22]), "=r"(r[23]), "=r"(r[24]), "=r"(r[25]), "=r"(r[26]),
        "=r"(r[27]), "=r"(r[28]), "=r"(r[29]), "=r"(r[30]), "=r"(r[31])
      : "r"(a));
}
__device__ __forceinline__ void ldtm_x16(uint32_t* r, uint32_t a) {
  asm volatile(
      "tcgen05.ld.sync.aligned.32x32b.x16.b32 "
      "{%0,%1,%2,%3,%4,%5,%6,%7,%8,%9,%10,%11,%12,%13,%14,%15}, [%16];"
      : "=r"(r[0]), "=r"(r[1]), "=r"(r[2]), "=r"(r[3]), "=r"(r[4]), "=r"(r[5]),
        "=r"(r[6]), "=r"(r[7]), "=r"(r[8]), "=r"(r[9]), "=r"(r[10]), "=r"(r[11]),
        "=r"(r[12]), "=r"(r[13]), "=r"(r[14]), "=r"(r[15])
      : "r"(a));
}
#endif  // LSTM_TC

// ---- prep: split/tile/swizzle weights & z; biases; zero state -----------
__global__ void prep_kernel(const float* __restrict__ z,
                            const float* __restrict__ Wih0,
                            const float* __restrict__ Whh0,
                            const float* __restrict__ bih0,
                            const float* __restrict__ bhh0,
                            const float* __restrict__ Wih1,
                            const float* __restrict__ Whh1,
                            const float* __restrict__ bih1,
                            const float* __restrict__ bhh1) {
  const int stride = gridDim.x * blockDim.x;
  const int g0 = blockIdx.x * blockDim.x + threadIdx.x;
  const float* Ws[4] = {Wih0, Whh0, Wih1, Whh1};
  char* wHiB = (char*)g_WHi;
  char* wLoB = (char*)g_WLo;
  for (int idx = g0; idx < 4 * Np * Kp; idx += stride) {
    int k = idx % Kp;
    int rr = idx / Kp;
    int n = rr % Np;
    int mi = rr / Np;
    int h = n >> 2, gg = n & 3;
    float w = (k < Hd) ? Ws[mi][(gg * Hd + h) * Hd + k] : 0.f;
    __nv_bfloat16 hi = __float2bfloat16(w);
    int nt = n / BN, r = n % BN, kt = k / BK, cc = k % BK;
    size_t off = (size_t)mi * (Np * Kp * 2) + (size_t)(nt * NKT + kt) * B_TILE +
                 SW128(r * 128 + cc * 2);
    *(__nv_bfloat16*)(wHiB + off) = hi;
    *(__nv_bfloat16*)(wLoB + off) = __float2bfloat16(w - __bfloat162float(hi));
  }
  for (int idx = g0; idx < 2 * Np; idx += stride) {
    int n = idx % Np, cell = idx / Np;
    int h = n >> 2, gg = n & 3;
    g_bias[cell][n] = cell ? (bih1[gg * Hd + h] + bhh1[gg * Hd + h])
                           : (bih0[gg * Hd + h] + bhh0[gg * Hd + h]);
  }
  char* aHiB = (char*)g_actHi;
  char* aLoB = (char*)g_actLo;
  for (int idx = g0; idx < Bx * Kp; idx += stride) {
    int k = idx % Kp, m = idx / Kp;
    float v = (k < Hd) ? z[m * Hd + k] : 0.f;
    __nv_bfloat16 hi = __float2bfloat16(v);
    int mt = m / BM, r = m % BM, kt = k / BK, cc = k % BK;
    size_t off = (size_t)(mt * NKT + kt) * A_TILE + SW128(r * 128 + cc * 2);
    *(__nv_bfloat16*)(aHiB + off) = hi;
    *(__nv_bfloat16*)(aLoB + off) = __float2bfloat16(v - __bfloat162float(hi));
  }
  // zero h buffers (1..4) vectorized; zero c
  uint4* zh = (uint4*)(g_actHi[1]);
  uint4* zl = (uint4*)(g_actLo[1]);
  const int nq = 4 * Bx * Kp * 2 / 16;
  uint4 zz = {0u, 0u, 0u, 0u};
  for (int idx = g0; idx < nq; idx += stride) { zh[idx] = zz; zl[idx] = zz; }
  for (int idx = g0; idx < Hd * Bx; idx += stride) {
    g_c[0][idx] = 0.f;
    g_c[1][idx] = 0.f;
  }
}

// ---- main fused GEMM + LSTM-cell kernel ---------------------------------
__global__ __launch_bounds__(256)
void lstm_tc_kernel(const __nv_bfloat16* __restrict__ Xhi,   // tiled act
                    const __nv_bfloat16* __restrict__ Xlo,
                    const __nv_bfloat16* __restrict__ Rhi,
                    const __nv_bfloat16* __restrict__ Rlo,
                    const __nv_bfloat16* __restrict__ WihHi,  // tiled weights
                    const __nv_bfloat16* __restrict__ WihLo,
                    const __nv_bfloat16* __restrict__ WhhHi,
                    const __nv_bfloat16* __restrict__ WhhLo,
                    const float* __restrict__ bias, float* __restrict__ C,
                    __nv_bfloat16* __restrict__ HoHi,         // tiled act out
                    __nv_bfloat16* __restrict__ HoLo, float* __restrict__ Y,
                    int t) {
  extern __shared__ __align__(1024) char smem[];
  const uint32_t sbase = (uint32_t)__cvta_generic_to_shared(smem);
  const int tid = threadIdx.x;
  const int wid = tid >> 5, lid = tid & 31;
  const int mt = blockIdx.x;
  const int nt = blockIdx.y;
  const int m0 = mt * BM;

#if LSTM_TC
  if (wid == 0) {
    asm volatile(
        "tcgen05.alloc.cta_group::1.sync.aligned.shared::cta.b32 [%0], %1;"
        :: "r"(sbase + SM_TMEM), "r"(256u) : "memory");
  }
  if (tid == 0) {
    #pragma unroll
    for (int s = 0; s < 2; ++s) {
      asm volatile("mbarrier.init.shared.b64 [%0], 1;"
                   :: "r"(sbase + SM_FULL + 8 * s) : "memory");
      asm volatile("mbarrier.init.shared.b64 [%0], 1;"
                   :: "r"(sbase + SM_DONE + 8 * s) : "memory");
    }
  }
#endif
  if (tid < BN) {
    ((float*)(smem + SM_BIAS))[tid] = bias[nt * BN + tid];
  }
  __syncthreads();

#if LSTM_TC
  uint32_t tmem_base;
  asm volatile("ld.shared.b32 %0, [%1];"
               : "=r"(tmem_base) : "r"(sbase + SM_TMEM));
  const uint32_t dD = tmem_base;  // D cols [0,240)

  // ---- single-warp 2-stage TMA->MMA pipeline ----------------------------
  if (wid == 0) {
    const char* Asrc[2][2] = {{(const char*)Xhi, (const char*)Xlo},
                              {(const char*)Rhi, (const char*)Rlo}};
    const char* Bsrc[2][2] = {{(const char*)WihHi, (const char*)WihLo},
                              {(const char*)WhhHi, (const char*)WhhLo}};
    const bool l0 = (lid == 0);

    auto issue_load = [&](int it2) {
      const int phl = (it2 >= NKT) ? 1 : 0;
      const int ktt = it2 - phl * NKT;
      const int s = it2 & 1;
      const uint32_t stb = sbase + SM_STAGE0 + s * STAGE_SZ;
      const uint32_t mb = sbase + SM_FULL + 8 * s;
      if (l0) {
        asm volatile("mbarrier.arrive.expect_tx.shared.b64 _, [%0], %1;"
                     :: "r"(mb), "r"((uint32_t)STAGE_SZ) : "memory");
        const size_t aoff = (size_t)(mt * NKT + ktt) * A_TILE;
        const size_t boff = (size_t)(nt * NKT + ktt) * B_TILE;
        bulk_cp(stb + ST_A_HI, Asrc[phl][0] + aoff, A_TILE, mb);
        bulk_cp(stb + ST_A_LO, Asrc[phl][1] + aoff, A_TILE, mb);
        bulk_cp(stb + ST_B_HI, Bsrc[phl][0] + boff, B_TILE, mb);
        bulk_cp(stb + ST_B_LO, Bsrc[phl][1] + boff, B_TILE, mb);
      }
    };

    issue_load(0);
    issue_load(1);
    #pragma unroll 1
    for (int j = 0; j < NIT; ++j) {
      const int s = j & 1;
      mbar_wait(sbase + SM_FULL + 8 * s, (uint32_t)((j >> 1) & 1));
      if (l0) {
        const uint32_t stb = sbase + SM_STAGE0 + s * STAGE_SZ;
        unsigned long long dAh = DESC_BASE | (((stb + ST_A_HI) >> 4) & 0x3FFF);
        unsigned long long dAl = DESC_BASE | (((stb + ST_A_LO) >> 4) & 0x3FFF);
        unsigned long long dBh = DESC_BASE | (((stb + ST_B_HI) >> 4) & 0x3FFF);
        unsigned long long dBl = DESC_BASE | (((stb + ST_B_LO) >> 4) & 0x3FFF);
        #pragma unroll
        for (int k16 = 0; k16 < 4; ++k16) {
          unsigned long long off = k16 * 2;  // 32B in 16B units
          #pragma unroll
          for (int half = 0; half < 2; ++half) {
            unsigned long long bo = off + half * 960;  // +120 rows = 15360B/16
            uint32_t dDh = dD + half * 120;
            mma_f16_ss(dDh, dAh + off, dBh + bo, !(j == 0 && k16 == 0));
            mma_f16_ss(dDh, dAh + off, dBl + bo, 1);
            mma_f16_ss(dDh, dAl + off, dBh + bo, 1);
          }
        }
        asm volatile(
            "tcgen05.commit.cta_group::1.mbarrier::arrive::one.shared::cluster.b64 [%0];"
            :: "r"(sbase + SM_DONE + 8 * s) : "memory");
      }
      if (j + 2 < NIT) {
        // stage s is recycled by load j+2 once MMA(j) committed
        mbar_wait(sbase + SM_DONE + 8 * s, (uint32_t)((j >> 1) & 1));
        issue_load(j + 2);
      }
    }
    // final commit (FIFO => all MMAs complete); j=NIT-1=9 -> s=1, 5th commit
    mbar_wait(sbase + SM_DONE + 8 * ((NIT - 1) & 1),
              (uint32_t)(((NIT - 1) >> 1) & 1));
  }
  __syncthreads();

  // ---- fused LSTM epilogue (warps 0-3 read TMEM subpartitions) ----------
  __nv_bfloat16* hst_hi = (__nv_bfloat16*)(smem + EP_HHI);
  __nv_bfloat16* hst_lo = (__nv_bfloat16*)(smem + EP_HLO);
  float* yst = (float*)(smem + EP_Y);
  if (wid < 4) {
    asm volatile("tcgen05.fence::after_thread_sync;" ::: "memory");
    const int ml = wid * 32 + lid;   // local row
    const int m = m0 + ml;
    const float* bsm = (const float*)(smem + SM_BIAS);
    const int hg0 = nt * NH;
    uint32_t r[32];
    #pragma unroll 1
    for (int cbi = 0; cbi < 8; ++cbi) {
      const int cb = cbi * 32;
      const int nh = (cbi < 7) ? 8 : 4;      // 240 cols = 7*32 + 16
      if (cbi < 7) ldtm_x32(r, dD + cb);
      else         ldtm_x16(r, dD + cb);
      asm volatile("tcgen05.wait::ld.sync.aligned;" ::: "memory");
      #pragma unroll
      for (int j = 0; j < 8; ++j) {
        if (j >= nh) break;
        const int col = cb + j * 4;
        const int hgl = col >> 2;            // 0..59
        float vi = __uint_as_float(r[j * 4 + 0]) + bsm[col + 0];
        float vf = __uint_as_float(r[j * 4 + 1]) + bsm[col + 1];
        float vg = __uint_as_float(r[j * 4 + 2]) + bsm[col + 2];
        float vo = __uint_as_float(r[j * 4 + 3]) + bsm[col + 3];
        float i_ = sigmoid_f(vi);
        float f_ = sigmoid_f(vf);
        float g_ = tanh_f(vg);
        float o_ = sigmoid_f(vo);
        size_t ci = (size_t)(hg0 + hgl) * Bx + m;
        float c = f_ * C[ci] + i_ * g_;
        float h = o_ * tanh_f(c);
        C[ci] = c;
        __nv_bfloat16 hi = __float2bfloat16(h);
        hst_hi[ml * NH + hgl] = hi;
        hst_lo[ml * NH + hgl] = __float2bfloat16(h - __bfloat162float(hi));
        yst[ml * NH + hgl] = h;
      }
    }
  }
  __syncthreads();
  // ---- vectorized copy-out of staged h (bf16 pairs) and y (float4) ------
  {
    const int hg0 = nt * NH;
    char* hoHiB = (char*)HoHi;
    char* hoLoB = (char*)HoLo;
    // h: 128 rows x 30 bf16-pairs (4B each). SW128 only mixes bits>=4, so a
    // 4B-aligned pair stays contiguous under the swizzle.
    for (int e = tid; e < BM * (NH / 2); e += 256) {
      int m = e / (NH / 2), pj = e - m * (NH / 2);
      int hg = hg0 + 2 * pj;
      int kt2 = hg >> 6, cc = hg & 63;
      size_t off = (size_t)(mt * NKT + kt2) * A_TILE + SW128(m * 128 + cc * 2);
      uint32_t vh = *(const uint32_t*)((const char*)hst_hi + m * NH * 2 + pj * 4);
      uint32_t vl = *(const uint32_t*)((const char*)hst_lo + m * NH * 2 + pj * 4);
      *(uint32_t*)(hoHiB + off) = vh;
      *(uint32_t*)(hoLoB + off) = vl;
    }
    if (Y) {
      // y: 128 rows x 15 float4 (60 floats/row), all 16B-aligned.
      for (int e = tid; e < BM * (NH / 4); e += 256) {
        int m = e / (NH / 4), q = e - m * (NH / 4);
        float4 v = *(const float4*)(yst + m * NH + q * 4);
        *(float4*)(Y + (size_t)(m0 + m) * (Tn * Hd) + (size_t)t * Hd + hg0 +
                   q * 4) = v;
      }
    }
  }
  __syncthreads();
  if (tid == 0) {
    #pragma unroll
    for (int s = 0; s < 2; ++s) {
      asm volatile("mbarrier.inval.shared.b64 [%0];"
                   :: "r"(sbase + SM_FULL + 8 * s) : "memory");
      asm volatile("mbarrier.inval.shared.b64 [%0];"
                   :: "r"(sbase + SM_DONE + 8 * s) : "memory");
    }
  }
  if (wid == 0) {
    asm volatile("tcgen05.relinquish_alloc_permit.cta_group::1.sync.aligned;");
    asm volatile("tcgen05.dealloc.cta_group::1.sync.aligned.b32 %0, %1;"
                 :: "r"(tmem_base), "r"(256u));
  }
#else
  // ---- SIMT fallback: read tiled global directly, accumulate fp32 -------
  float facc[NH * 2];  // 120 cols per thread-half
  for (int i = 0; i < NH * 2; ++i) facc[i] = 0.f;
  const int f_row = tid >> 1;
  const int f_ch = tid & 1;  // cols [f_ch*120, +120)
  const char* Asrc[2][2] = {{(const char*)Xhi, (const char*)Xlo},
                            {(const char*)Rhi, (const char*)Rlo}};
  const char* Bsrc[2][2] = {{(const char*)WihHi, (const char*)WihLo},
                            {(const char*)WhhHi, (const char*)WhhLo}};
  for (int it = 0; it < NIT; ++it) {
    int phl = (it >= NKT) ? 1 : 0;
    int ktt = it - phl * NKT;
    size_t at = (size_t)(mt * NKT + ktt) * A_TILE;
    size_t bt = (size_t)(nt * NKT + ktt) * B_TILE;
    for (int k = 0; k < BK; ++k) {
      uint32_t ao = SW128(f_row * 128 + k * 2);
      float a =
          __bfloat162float(*(const __nv_bfloat16*)(Asrc[phl][0] + at + ao)) +
          __bfloat162float(*(const __nv_bfloat16*)(Asrc[phl][1] + at + ao));
      for (int c = 0; c < 120; ++c) {
        int bn = f_ch * 120 + c;
        uint32_t bo = SW128(bn * 128 + k * 2);
        float b =
            __bfloat162float(*(const __nv_bfloat16*)(Bsrc[phl][0] + bt + bo)) +
            __bfloat162float(*(const __nv_bfloat16*)(Bsrc[phl][1] + bt + bo));
        facc[c] = fmaf(a, b, facc[c]);
      }
    }
  }
  {
    const float* bsm = (const float*)(smem + SM_BIAS);
    const int m = m0 + f_row;
    char* hoHiB = (char*)HoHi;
    char* hoLoB = (char*)HoLo;
    for (int jh = 0; jh < 30; ++jh) {
      int col = f_ch * 120 + jh * 4;
      int hg = nt * NH + (col >> 2);
      float i_ = sigmoid_f(facc[jh * 4 + 0] + bsm[col + 0]);
      float f_ = sigmoid_f(facc[jh * 4 + 1] + bsm[col + 1]);
      float g_ = tanh_f(facc[jh * 4 + 2] + bsm[col + 2]);
      float o_ = sigmoid_f(facc[jh * 4 + 3] + bsm[col + 3]);
      size_t ci = (size_t)hg * Bx + m;
      float c = f_ * C[ci] + i_ * g_;
      float h = o_ * tanh_f(c);
      C[ci] = c;
      const int kt2 = hg >> 6, cc = hg & 63;
      size_t off = (size_t)(mt * NKT + kt2) * A_TILE + SW128(f_row * 128 + cc * 2);
      __nv_bfloat16 hi = __float2bfloat16(h);
      *(__nv_bfloat16*)(hoHiB + off) = hi;
      *(__nv_bfloat16*)(hoLoB + off) = __float2bfloat16(h - __bfloat162float(hi));
      if (Y) Y[(size_t)m * (Tn * Hd) + (size_t)t * Hd + hg] = h;
    }
  }
  (void)wid; (void)lid;
#endif
}

// ---- host side ----------------------------------------------------------
extern "C" void kernel_launch(void* const* d_in, const int* in_sizes, int n_in,
                              void* d_out, int out_size) {
  const float* z    = (const float*)d_in[0];
  const float* Wih0 = (const float*)d_in[1];
  const float* Whh0 = (const float*)d_in[2];
  const float* bih0 = (const float*)d_in[3];
  const float* bhh0 = (const float*)d_in[4];
  const float* Wih1 = (const float*)d_in[5];
  const float* Whh1 = (const float*)d_in[6];
  const float* bih1 = (const float*)d_in[7];
  const float* bhh1 = (const float*)d_in[8];
  float* out = (float*)d_out;

  cudaFuncSetAttribute(lstm_tc_kernel,
                       cudaFuncAttributeMaxDynamicSharedMemorySize, SM_TOTAL);

  void* p;
  cudaGetSymbolAddress(&p, g_WHi);   __nv_bfloat16* wHi = (__nv_bfloat16*)p;
  cudaGetSymbolAddress(&p, g_WLo);   __nv_bfloat16* wLo = (__nv_bfloat16*)p;
  cudaGetSymbolAddress(&p, g_bias);  float* bias = (float*)p;
  cudaGetSymbolAddress(&p, g_actHi); __nv_bfloat16* aHi = (__nv_bfloat16*)p;
  cudaGetSymbolAddress(&p, g_actLo); __nv_bfloat16* aLo = (__nv_bfloat16*)p;
  cudaGetSymbolAddress(&p, g_c);     float* cst = (float*)p;

  const size_t WS = (size_t)Np * Kp;   // one weight matrix (elements)
  const size_t AS = (size_t)Bx * Kp;   // one activation buffer (elements)
  const size_t CS = (size_t)Hd * Bx;

  prep_kernel<<<1024, 256>>>(z, Wih0, Whh0, bih0, bhh0, Wih1, Whh1, bih1, bhh1);

  dim3 grid(NMT, NNT);  // 32 x 5
  for (int t = 0; t < Tn; ++t) {
    int cur = t & 1, nxt = cur ^ 1;
    // act buffer ids: 0=z, 1/2=h0 ping-pong, 3/4=h1 ping-pong
    const __nv_bfloat16* x0hi = (t == 0) ? aHi : aHi + (3 + cur) * AS;
    const __nv_bfloat16* x0lo = (t == 0) ? aLo : aLo + (3 + cur) * AS;
    lstm_tc_kernel<<<grid, 256, SM_TOTAL>>>(
        x0hi, x0lo, aHi + (1 + cur) * AS, aLo + (1 + cur) * AS,
        wHi + 0 * WS, wLo + 0 * WS, wHi + 1 * WS, wLo + 1 * WS,
        bias, cst, aHi + (1 + nxt) * AS, aLo + (1 + nxt) * AS, nullptr, t);
    lstm_tc_kernel<<<grid, 256, SM_TOTAL>>>(
        aHi + (1 + nxt) * AS, aLo + (1 + nxt) * AS,
        aHi + (3 + cur) * AS, aLo + (3 + cur) * AS,
        wHi + 2 * WS, wLo + 2 * WS, wHi + 3 * WS, wLo + 3 * WS,
        bias + Np, cst + CS, aHi + (3 + nxt) * AS, aLo + (3 + nxt) * AS, out, t);
  }
}

// round 15
// speedup vs baseline: 2.8987x; 1.0525x over previous
#include <cuda_runtime.h>
#include <cuda_bf16.h>
#include <cstdint>

// 2-layer LSTM, B=4096, H=300, T=64 — ONE persistent kernel over all 128
// cell-steps (64 t x 2 layers). tcgen05 bf16-split MMA (hi*hi+hi*lo+lo*hi),
// D in TMEM fp32. Per CTA: M=128 x N=304 (300 real + 4 pad), grid 32x4 = 128
// CTAs <= 148 SMs -> all co-resident -> device-wide atomic barrier between
// cells. 2-stage TMA->MMA pipeline with SEPARATE FULL_A/FULL_B mbarriers so
// next cell's weight tile is prefetched across the barrier (overlaps the
// epilogue). All SW128 descriptor bases 1024-aligned.

#if defined(__CUDA_ARCH_FEAT_SM103_ALL) || defined(__CUDA_ARCH_FEAT_SM100_ALL) || \
    defined(__CUDA_ARCH_FEAT_SM101_ALL) ||                                        \
    (defined(__CUDA_ARCH_FAMILY_SPECIFIC__) && (__CUDA_ARCH_FAMILY_SPECIFIC__ >= 1000))
#define LSTM_TC 1
#else
#define LSTM_TC 0
#endif

#define SW128(o) ((o) ^ (((o) >> 3) & 0x70))

namespace {
constexpr int Bx = 4096, Hd = 300, Tn = 64;
constexpr int Kp = 320;               // padded K per phase
constexpr int BM = 128, BNp = 304, BK = 64;  // BNp: 300 real cols + 4 pad
constexpr int NHs = 75;               // real h-groups per CTA (300/4)
constexpr int NKT = 5;                // k-tiles per phase
constexpr int NIT = 10;               // iterations per cell (2 phases x 5)
constexpr int NMT = Bx / BM;          // 32
constexpr int NNT = 4;                // 1200/300
constexpr int CELLS = 2 * Tn;         // 128
constexpr int A_TILE = BM * 128;      // 16384
constexpr int B_TILE = BNp * 128;     // 38912
constexpr int WMAT = NNT * NKT * BNp * BK;  // elems per weight matrix (389120)
constexpr unsigned IDESC = (1u << 4) | (1u << 7) | (1u << 10) |
                           ((152 / 8) << 17) | ((BM / 16) << 24);  // N=152/MMA
constexpr unsigned long long DESC_BASE =  // SW128, Blackwell, SBO=64, LBO=1
    (2ull << 61) | (1ull << 46) | (64ull << 32) | (1ull << 16);
// smem head
constexpr int SM_TMEM = 0;
constexpr int SM_FULLA = 8;           // 2 mbarriers: 8,16
constexpr int SM_FULLB = 24;          // 2 mbarriers: 24,32
constexpr int SM_DONE = 40;           // 2 mbarriers: 40,48
constexpr int SM_BIAS = 64;           // 2 cells x 304 floats = 2432 B
constexpr int ST_A_HI = 0;
constexpr int ST_A_LO = A_TILE;               // 16384
constexpr int ST_B_HI = 2 * A_TILE;           // 32768
constexpr int ST_B_LO = 2 * A_TILE + B_TILE;  // 71680
constexpr int STAGE_SZ = 2 * A_TILE + 2 * B_TILE;  // 110592 = 108*1024
constexpr int SM_STAGE0 = 4096;
constexpr int SM_TOTAL = SM_STAGE0 + 2 * STAGE_SZ;  // 225280 (220 KiB)
// epilogue staging lives in STAGE 1 (free after final DONE; stage0 hosts the
// cross-barrier B prefetch)
constexpr int EP_HHI = SM_STAGE0 + STAGE_SZ;            // 114688
constexpr int EP_HLO = EP_HHI + BM * NHs * 2;           // +19200
constexpr int EP_Y   = EP_HLO + BM * NHs * 2;           // +19200 (ends 191488)
}

// ---- persistent device state -------------------------------------------
__device__ __align__(1024) __nv_bfloat16 g_WHi[4][WMAT];  // ih0,hh0,ih1,hh1
__device__ __align__(1024) __nv_bfloat16 g_WLo[4][WMAT];
// act buffers: 0=z, 1/2=h0 ping-pong, 3/4=h1 ping-pong; tiled [mt][kt]
__device__ __align__(1024) __nv_bfloat16 g_actHi[5][Bx * Kp];
__device__ __align__(1024) __nv_bfloat16 g_actLo[5][Bx * Kp];
__device__ float g_bias[2][4 * Hd];
__device__ float g_c[2][Hd * Bx];
__device__ unsigned g_bar;

// ---- helpers ------------------------------------------------------------
__device__ __forceinline__ float sigmoid_f(float v) {
  return __fdividef(1.0f, 1.0f + __expf(-v));
}
__device__ __forceinline__ float tanh_f(float v) {
  return 2.0f * __fdividef(1.0f, 1.0f + __expf(-2.0f * v)) - 1.0f;
}

// device-wide barrier: 128 co-resident CTAs, monotonic epoch counter.
__device__ __forceinline__ void grid_barrier(int epoch, int tid) {
  __threadfence();
  __syncthreads();
  if (tid == 0) {
    atomicAdd(&g_bar, 1u);
    const unsigned target = 128u * (unsigned)epoch;
    unsigned v = 0, spins = 0;
    do {
      asm volatile("ld.acquire.gpu.u32 %0, [%1];" : "=r"(v) : "l"(&g_bar)
                   : "memory");
    } while (v < target && ++spins < (1u << 20));  // bounded: no hard hang
  }
  __syncthreads();
}

#if LSTM_TC
__device__ __forceinline__ void mma_f16_ss(uint32_t d, unsigned long long da,
                                           unsigned long long db, uint32_t en) {
  asm volatile(
      "{\n\t.reg .pred p;\n\tsetp.ne.u32 p, %4, 0;\n\t"
      "tcgen05.mma.cta_group::1.kind::f16 [%0], %1, %2, %3, {%5, %5, %5, %5}, p;\n\t}"
      :: "r"(d), "l"(da), "l"(db), "r"(IDESC), "r"(en), "r"(0u) : "memory");
}
__device__ __forceinline__ void mbar_wait(uint32_t mbar, uint32_t parity) {
  uint32_t done;
  asm volatile(
      "{\n\t.reg .pred p;\n\t"
      "mbarrier.try_wait.parity.acquire.cta.shared::cta.b64 p, [%1], %2;\n\t"
      "selp.b32 %0, 1, 0, p;\n\t}"
      : "=r"(done) : "r"(mbar), "r"(parity) : "memory");
  if (!done) {
    asm volatile(
        "{\n\t.reg .pred P1;\n\t"
        "W_%=:\n\t"
        "mbarrier.try_wait.parity.acquire.cta.shared::cta.b64 P1, [%0], %1, 0x989680;\n\t"
        "@P1 bra.uni D_%=;\n\t"
        "bra.uni W_%=;\n\t"
        "D_%=:\n\t}"
        :: "r"(mbar), "r"(parity) : "memory");
  }
}
__device__ __forceinline__ void bulk_cp(uint32_t dst, const void* src,
                                        uint32_t bytes, uint32_t mbar) {
  asm volatile(
      "cp.async.bulk.shared::cta.global.mbarrier::complete_tx::bytes "
      "[%0], [%1], %2, [%3];"
      :: "r"(dst), "l"(src), "r"(bytes), "r"(mbar) : "memory");
}
__device__ __forceinline__ void expect_tx(uint32_t mbar, uint32_t bytes) {
  asm volatile("mbarrier.arrive.expect_tx.shared.b64 _, [%0], %1;"
               :: "r"(mbar), "r"(bytes) : "memory");
}
__device__ __forceinline__ void ldtm_x32(uint32_t* r, uint32_t a) {
  asm volatile(
      "tcgen05.ld.sync.aligned.32x32b.x32.b32 "
      "{%0,%1,%2,%3,%4,%5,%6,%7,%8,%9,%10,%11,%12,%13,%14,%15,"
      "%16,%17,%18,%19,%20,%21,%22,%23,%24,%25,%26,%27,%28,%29,%30,%31}, [%32];"
      : "=r"(r[0]), "=r"(r[1]), "=r"(r[2]), "=r"(r[3]), "=r"(r[4]), "=r"(r[5]),
        "=r"(r[6]), "=r"(r[7]), "=r"(r[8]), "=r"(r[9]), "=r"(r[10]), "=r"(r[11]),
        "=r"(r[12]), "=r"(r[13]), "=r"(r[14]), "=r"(r[15]), "=r"(r[16]),
        "=r"(r[17]), "=r"(r[18]), "=r"(r[19]), "=r"(r[20]), "=r"(r[21]),
        "=r"(r[22]), "=r"(r[23]), "=r"(r[24]), "=r"(r[25]), "=r"(r[26]),
        "=r"(r[27]), "=r"(r[28]), "=r"(r[29]), "=r"(r[30]), "=r"(r[31])
      : "r"(a));
}
__device__ __forceinline__ void ldtm_x16(uint32_t* r, uint32_t a) {
  asm volatile(
      "tcgen05.ld.sync.aligned.32x32b.x16.b32 "
      "{%0,%1,%2,%3,%4,%5,%6,%7,%8,%9,%10,%11,%12,%13,%14,%15}, [%16];"
      : "=r"(r[0]), "=r"(r[1]), "=r"(r[2]), "=r"(r[3]), "=r"(r[4]), "=r"(r[5]),
        "=r"(r[6]), "=r"(r[7]), "=r"(r[8]), "=r"(r[9]), "=r"(r[10]), "=r"(r[11]),
        "=r"(r[12]), "=r"(r[13]), "=r"(r[14]), "=r"(r[15])
      : "r"(a));
}
#endif  // LSTM_TC

// activation buffer ids for a cell
__device__ __forceinline__ void cell_bufs(int cell, int& xb, int& rb, int& hob) {
  int L = cell & 1, t = cell >> 1, cur = t & 1, nxt = cur ^ 1;
  if (L == 0) {
    xb = (t == 0) ? 0 : (3 + cur);
    rb = 1 + cur;
    hob = 1 + nxt;
  } else {
    xb = 1 + nxt;
    rb = 3 + cur;
    hob = 3 + nxt;
  }
}

// ---- prep ---------------------------------------------------------------
__global__ void prep_kernel(const float* __restrict__ z,
                            const float* __restrict__ Wih0,
                            const float* __restrict__ Whh0,
                            const float* __restrict__ bih0,
                            const float* __restrict__ bhh0,
                            const float* __restrict__ Wih1,
                            const float* __restrict__ Whh1,
                            const float* __restrict__ bih1,
                            const float* __restrict__ bhh1) {
  const int stride = gridDim.x * blockDim.x;
  const int g0 = blockIdx.x * blockDim.x + threadIdx.x;
  if (g0 == 0) g_bar = 0u;
  const float* Ws[4] = {Wih0, Whh0, Wih1, Whh1};
  char* wHiB = (char*)g_WHi;
  char* wLoB = (char*)g_WLo;
  for (int idx = g0; idx < 4 * WMAT; idx += stride) {
    int mi = idx / WMAT;
    int rem = idx - mi * WMAT;
    int tile = rem / (BNp * BK);
    int e = rem - tile * (BNp * BK);
    int r = e / BK, cc = e - (e / BK) * BK;
    int ntt = tile / NKT, ktt = tile - ntt * NKT;
    int k = ktt * BK + cc;
    float w = 0.f;
    if (r < 300 && k < Hd) {
      int n = ntt * 300 + r;
      int h = n >> 2, gg = n & 3;
      w = Ws[mi][(gg * Hd + h) * Hd + k];
    }
    __nv_bfloat16 hi = __float2bfloat16(w);
    size_t off = (size_t)mi * (4ull * WMAT / 2) * 2 +  // mi*WMAT*2 bytes
                 (size_t)tile * B_TILE + SW128(r * 128 + cc * 2);
    off = (size_t)mi * ((size_t)WMAT * 2) + (size_t)tile * B_TILE +
          SW128(r * 128 + cc * 2);
    *(__nv_bfloat16*)(wHiB + off) = hi;
    *(__nv_bfloat16*)(wLoB + off) = __float2bfloat16(w - __bfloat162float(hi));
  }
  for (int idx = g0; idx < 2 * 4 * Hd; idx += stride) {
    int n = idx % (4 * Hd), cell = idx / (4 * Hd);
    int h = n >> 2, gg = n & 3;
    g_bias[cell][n] = cell ? (bih1[gg * Hd + h] + bhh1[gg * Hd + h])
                           : (bih0[gg * Hd + h] + bhh0[gg * Hd + h]);
  }
  char* aHiB = (char*)g_actHi;
  char* aLoB = (char*)g_actLo;
  for (int idx = g0; idx < Bx * Kp; idx += stride) {
    int k = idx % Kp, m = idx / Kp;
    float v = (k < Hd) ? z[m * Hd + k] : 0.f;
    __nv_bfloat16 hi = __float2bfloat16(v);
    int mt = m / BM, r = m % BM, kt = k / BK, cc = k % BK;
    size_t off = (size_t)(mt * NKT + kt) * A_TILE + SW128(r * 128 + cc * 2);
    *(__nv_bfloat16*)(aHiB + off) = hi;
    *(__nv_bfloat16*)(aLoB + off) = __float2bfloat16(v - __bfloat162float(hi));
  }
  uint4* zh = (uint4*)(g_actHi[1]);
  uint4* zl = (uint4*)(g_actLo[1]);
  const int nq = 4 * Bx * Kp * 2 / 16;
  uint4 zz = {0u, 0u, 0u, 0u};
  for (int idx = g0; idx < nq; idx += stride) { zh[idx] = zz; zl[idx] = zz; }
  for (int idx = g0; idx < Hd * Bx; idx += stride) {
    g_c[0][idx] = 0.f;
    g_c[1][idx] = 0.f;
  }
}

// ---- persistent fused kernel --------------------------------------------
__global__ __launch_bounds__(256) void lstm_persist_kernel(float* __restrict__ Y) {
  extern __shared__ __align__(1024) char smem[];
  const uint32_t sbase = (uint32_t)__cvta_generic_to_shared(smem);
  const int tid = threadIdx.x;
  const int wid = tid >> 5, lid = tid & 31;
  const int mt = blockIdx.x;   // 0..31
  const int nt = blockIdx.y;   // 0..3
  const int m0 = mt * BM;

#if LSTM_TC
  if (wid == 0) {
    asm volatile(
        "tcgen05.alloc.cta_group::1.sync.aligned.shared::cta.b32 [%0], %1;"
        :: "r"(sbase + SM_TMEM), "r"(512u) : "memory");
  }
  if (tid == 0) {
    #pragma unroll
    for (int s = 0; s < 2; ++s) {
      asm volatile("mbarrier.init.shared.b64 [%0], 1;"
                   :: "r"(sbase + SM_FULLA + 8 * s) : "memory");
      asm volatile("mbarrier.init.shared.b64 [%0], 1;"
                   :: "r"(sbase + SM_FULLB + 8 * s) : "memory");
      asm volatile("mbarrier.init.shared.b64 [%0], 1;"
                   :: "r"(sbase + SM_DONE + 8 * s) : "memory");
    }
  }
#endif
  // biases for BOTH cells of this nt-slice (pad cols -> 0)
  for (int i = tid; i < 2 * BNp; i += 256) {
    int L = i / BNp, col = i - L * BNp;
    float b = (col < 300) ? g_bias[L][nt * 300 + col] : 0.f;
    ((float*)(smem + SM_BIAS))[L * BNp + col] = b;
  }
  __syncthreads();

#if LSTM_TC
  uint32_t tmem_base;
  asm volatile("ld.shared.b32 %0, [%1];"
               : "=r"(tmem_base) : "r"(sbase + SM_TMEM));
  const uint32_t dD = tmem_base;  // D cols [0,304): halves at 0 and 152
  const bool l0 = (lid == 0);

  // ---- load issuers (producer warp only) --------------------------------
  auto issueA = [&](int G) {
    if (!l0) return;
    int c = G / NIT, j = G - (G / NIT) * NIT;
    int ph = (j >= NKT), kt = j - ph * NKT, s = j & 1;
    int xb, rb, hob;
    cell_bufs(c, xb, rb, hob);
    int ab = ph ? rb : xb;
    const char* ah = (const char*)g_actHi[ab];
    const char* al = (const char*)g_actLo[ab];
    uint32_t stb = sbase + SM_STAGE0 + s * STAGE_SZ;
    uint32_t mb = sbase + SM_FULLA + 8 * s;
    expect_tx(mb, 2 * A_TILE);
    size_t aoff = (size_t)(mt * NKT + kt) * A_TILE;
    bulk_cp(stb + ST_A_HI, ah + aoff, A_TILE, mb);
    bulk_cp(stb + ST_A_LO, al + aoff, A_TILE, mb);
  };
  auto issueB = [&](int G) {
    if (!l0) return;
    int c = G / NIT, j = G - (G / NIT) * NIT;
    int ph = (j >= NKT), kt = j - ph * NKT, s = j & 1;
    int mi = 2 * (c & 1) + ph;
    const char* bh = (const char*)g_WHi[mi];
    const char* bl = (const char*)g_WLo[mi];
    uint32_t stb = sbase + SM_STAGE0 + s * STAGE_SZ;
    uint32_t mb = sbase + SM_FULLB + 8 * s;
    expect_tx(mb, 2 * B_TILE);
    size_t boff = (size_t)(nt * NKT + kt) * B_TILE;
    bulk_cp(stb + ST_B_HI, bh + boff, B_TILE, mb);
    bulk_cp(stb + ST_B_LO, bl + boff, B_TILE, mb);
  };

  __nv_bfloat16* hst_hi = (__nv_bfloat16*)(smem + EP_HHI);
  __nv_bfloat16* hst_lo = (__nv_bfloat16*)(smem + EP_HLO);
  float* yst = (float*)(smem + EP_Y);

  #pragma unroll 1
  for (int cell = 0; cell < CELLS; ++cell) {
    const int G0 = cell * NIT;
    const int L = cell & 1, t = cell >> 1;
    int xb, rb, hob;
    cell_bufs(cell, xb, rb, hob);
    float* C = g_c[L];
    const float* bsm = (const float*)(smem + SM_BIAS) + L * BNp;

    if (wid == 0) {
      if (cell == 0) {
        issueB(0); issueA(0); issueB(1); issueA(1);
      } else {
        // B(G0) was prefetched across the barrier; A now that h is ready.
        asm volatile("fence.proxy.async;" ::: "memory");
        issueA(G0); issueB(G0 + 1); issueA(G0 + 1);
      }
      #pragma unroll 1
      for (int j = 0; j < NIT; ++j) {
        const int G = G0 + j;
        const int s = j & 1;
        const uint32_t par = (uint32_t)((G >> 1) & 1);
        mbar_wait(sbase + SM_FULLB + 8 * s, par);
        mbar_wait(sbase + SM_FULLA + 8 * s, par);
        if (l0) {
          const uint32_t stb = sbase + SM_STAGE0 + s * STAGE_SZ;
          unsigned long long dAh = DESC_BASE | (((stb + ST_A_HI) >> 4) & 0x3FFF);
          unsigned long long dAl = DESC_BASE | (((stb + ST_A_LO) >> 4) & 0x3FFF);
          unsigned long long dBh = DESC_BASE | (((stb + ST_B_HI) >> 4) & 0x3FFF);
          unsigned long long dBl = DESC_BASE | (((stb + ST_B_LO) >> 4) & 0x3FFF);
          #pragma unroll
          for (int k16 = 0; k16 < 4; ++k16) {
            unsigned long long off = k16 * 2;
            uint32_t en0 = !(j == 0 && k16 == 0);
            #pragma unroll
            for (int half = 0; half < 2; ++half) {
              unsigned long long bo = off + half * 1216;  // +152 rows
              uint32_t dDh = dD + half * 152;
              mma_f16_ss(dDh, dAh + off, dBh + bo, en0);
              mma_f16_ss(dDh, dAh + off, dBl + bo, 1);
              mma_f16_ss(dDh, dAl + off, dBh + bo, 1);
            }
          }
          asm volatile(
              "tcgen05.commit.cta_group::1.mbarrier::arrive::one.shared::cluster.b64 [%0];"
              :: "r"(sbase + SM_DONE + 8 * s) : "memory");
        }
        if (j <= NIT - 3) {
          mbar_wait(sbase + SM_DONE + 8 * s, par);  // stage s free
          issueB(G + 2);
          issueA(G + 2);
        }
      }
      // drain: stage0 (G0+8) then stage1 (G0+9); prefetch next cell's B(j=0)
      if (cell < CELLS - 1) {
        mbar_wait(sbase + SM_DONE + 0, (uint32_t)(((G0 + 8) >> 1) & 1));
        issueB(G0 + NIT);  // next cell, stage 0 — overlaps epilogue+barrier
      }
      mbar_wait(sbase + SM_DONE + 8, (uint32_t)(((G0 + 9) >> 1) & 1));
    }
    __syncthreads();

    // ---- fused LSTM epilogue (warps 0-3; staging in stage-1 area) -------
    if (wid < 4) {
      asm volatile("tcgen05.fence::after_thread_sync;" ::: "memory");
      const int ml = wid * 32 + lid;
      const int m = m0 + ml;
      const int hg0 = nt * NHs;
      uint32_t r[32];
      #pragma unroll 1
      for (int cbi = 0; cbi < 10; ++cbi) {
        const int cb = cbi * 32;
        const int nh = (cbi < 9) ? 8 : 3;  // last block: cols 288..299 real
        if (cbi < 9) ldtm_x32(r, dD + cb);
        else         ldtm_x16(r, dD + cb);
        asm volatile("tcgen05.wait::ld.sync.aligned;" ::: "memory");
        #pragma unroll
        for (int j2 = 0; j2 < 8; ++j2) {
          if (j2 >= nh) break;
          const int col = cb + j2 * 4;
          const int hgl = col >> 2;
          float vi = __uint_as_float(r[j2 * 4 + 0]) + bsm[col + 0];
          float vf = __uint_as_float(r[j2 * 4 + 1]) + bsm[col + 1];
          float vg = __uint_as_float(r[j2 * 4 + 2]) + bsm[col + 2];
          float vo = __uint_as_float(r[j2 * 4 + 3]) + bsm[col + 3];
          float i_ = sigmoid_f(vi);
          float f_ = sigmoid_f(vf);
          float g_ = tanh_f(vg);
          float o_ = sigmoid_f(vo);
          size_t ci = (size_t)(hg0 + hgl) * Bx + m;
          float c = f_ * C[ci] + i_ * g_;
          float h = o_ * tanh_f(c);
          C[ci] = c;
          __nv_bfloat16 hi = __float2bfloat16(h);
          hst_hi[ml * NHs + hgl] = hi;
          hst_lo[ml * NHs + hgl] = __float2bfloat16(h - __bfloat162float(hi));
          yst[ml * NHs + hgl] = h;
        }
      }
    }
    __syncthreads();
    // ---- copy-out (scalar; NHs=75 is odd, pairs could straddle k-tiles) --
    {
      char* hoHiB = (char*)g_actHi[hob];
      char* hoLoB = (char*)g_actLo[hob];
      for (int e = tid; e < BM * NHs; e += 256) {
        int m2 = e / NHs, j3 = e - (e / NHs) * NHs;
        int hg = nt * NHs + j3;
        int kt2 = hg >> 6, cc = hg & 63;
        size_t off = (size_t)(mt * NKT + kt2) * A_TILE + SW128(m2 * 128 + cc * 2);
        *(__nv_bfloat16*)(hoHiB + off) = hst_hi[e];
        *(__nv_bfloat16*)(hoLoB + off) = hst_lo[e];
      }
      if (L) {
        for (int e = tid; e < BM * NHs; e += 256) {
          int m2 = e / NHs, j3 = e - (e / NHs) * NHs;
          int hg = nt * NHs + j3;
          Y[(size_t)(m0 + m2) * (Tn * Hd) + (size_t)t * Hd + hg] = yst[e];
        }
      }
    }
    if (cell < CELLS - 1) grid_barrier(cell + 1, tid);
  }

  __syncthreads();
  if (tid == 0) {
    #pragma unroll
    for (int s = 0; s < 2; ++s) {
      asm volatile("mbarrier.inval.shared.b64 [%0];"
                   :: "r"(sbase + SM_FULLA + 8 * s) : "memory");
      asm volatile("mbarrier.inval.shared.b64 [%0];"
                   :: "r"(sbase + SM_FULLB + 8 * s) : "memory");
      asm volatile("mbarrier.inval.shared.b64 [%0];"
                   :: "r"(sbase + SM_DONE + 8 * s) : "memory");
    }
  }
  if (wid == 0) {
    asm volatile("tcgen05.relinquish_alloc_permit.cta_group::1.sync.aligned;");
    asm volatile("tcgen05.dealloc.cta_group::1.sync.aligned.b32 %0, %1;"
                 :: "r"(tmem_base), "r"(512u));
  }
#else
  // ---- SIMT fallback (compiles on non-'a' targets; correct, slow) -------
  const int f_row = tid >> 1;
  const int f_ch = tid & 1;  // cols [f_ch*152, +152)
  #pragma unroll 1
  for (int cell = 0; cell < CELLS; ++cell) {
    const int L = cell & 1, t = cell >> 1;
    int xb, rb, hob;
    cell_bufs(cell, xb, rb, hob);
    float* C = g_c[L];
    const float* bsm = (const float*)(smem + SM_BIAS) + L * BNp;
    float facc[152];
    for (int i = 0; i < 152; ++i) facc[i] = 0.f;
    for (int it = 0; it < NIT; ++it) {
      int ph = (it >= NKT), ktt = it - ph * NKT;
      int ab = ph ? rb : xb;
      int mi = 2 * L + ph;
      const char* ah = (const char*)g_actHi[ab];
      const char* al = (const char*)g_actLo[ab];
      const char* bh = (const char*)g_WHi[mi];
      const char* bl = (const char*)g_WLo[mi];
      size_t at = (size_t)(mt * NKT + ktt) * A_TILE;
      size_t bt = (size_t)(nt * NKT + ktt) * B_TILE;
      for (int k = 0; k < BK; ++k) {
        uint32_t ao = SW128(f_row * 128 + k * 2);
        float a = __bfloat162float(*(const __nv_bfloat16*)(ah + at + ao)) +
                  __bfloat162float(*(const __nv_bfloat16*)(al + at + ao));
        for (int c2 = 0; c2 < 152; ++c2) {
          int bn = f_ch * 152 + c2;
          uint32_t bo = SW128(bn * 128 + k * 2);
          float b = __bfloat162float(*(const __nv_bfloat16*)(bh + bt + bo)) +
                    __bfloat162float(*(const __nv_bfloat16*)(bl + bt + bo));
          facc[c2] = fmaf(a, b, facc[c2]);
        }
      }
    }
    {
      char* hoHiB = (char*)g_actHi[hob];
      char* hoLoB = (char*)g_actLo[hob];
      const int m = m0 + f_row;
      for (int jh = 0; jh < 38; ++jh) {
        int col = f_ch * 152 + jh * 4;
        if (col >= 300) break;
        int hg = nt * NHs + (col >> 2);
        float i_ = sigmoid_f(facc[jh * 4 + 0 - 0] + bsm[col + 0]);
        float f_ = sigmoid_f(facc[jh * 4 + 1] + bsm[col + 1]);
        float g_ = tanh_f(facc[jh * 4 + 2] + bsm[col + 2]);
        float o_ = sigmoid_f(facc[jh * 4 + 3] + bsm[col + 3]);
        size_t ci = (size_t)hg * Bx + m;
        float c = f_ * C[ci] + i_ * g_;
        float h = o_ * tanh_f(c);
        C[ci] = c;
        int kt2 = hg >> 6, cc = hg & 63;
        size_t off = (size_t)(mt * NKT + kt2) * A_TILE + SW128(f_row * 128 + cc * 2);
        __nv_bfloat16 hi = __float2bfloat16(h);
        *(__nv_bfloat16*)(hoHiB + off) = hi;
        *(__nv_bfloat16*)(hoLoB + off) =
            __float2bfloat16(h - __bfloat162float(hi));
        if (L) Y[(size_t)m * (Tn * Hd) + (size_t)t * Hd + hg] = h;
      }
    }
    if (cell < CELLS - 1) grid_barrier(cell + 1, tid);
  }
#endif
}

// ---- host side ----------------------------------------------------------
extern "C" void kernel_launch(void* const* d_in, const int* in_sizes, int n_in,
                              void* d_out, int out_size) {
  const float* z    = (const float*)d_in[0];
  const float* Wih0 = (const float*)d_in[1];
  const float* Whh0 = (const float*)d_in[2];
  const float* bih0 = (const float*)d_in[3];
  const float* bhh0 = (const float*)d_in[4];
  const float* Wih1 = (const float*)d_in[5];
  const float* Whh1 = (const float*)d_in[6];
  const float* bih1 = (const float*)d_in[7];
  const float* bhh1 = (const float*)d_in[8];
  float* out = (float*)d_out;

  cudaFuncSetAttribute(lstm_persist_kernel,
                       cudaFuncAttributeMaxDynamicSharedMemorySize, SM_TOTAL);

  prep_kernel<<<1024, 256>>>(z, Wih0, Whh0, bih0, bhh0, Wih1, Whh1, bih1, bhh1);

  dim3 grid(NMT, NNT);  // 32 x 4 = 128 CTAs <= 148 SMs (all co-resident)
  lstm_persist_kernel<<<grid, 256, SM_TOTAL>>>(out);
}

// round 16
// speedup vs baseline: 5.4696x; 1.8869x over previous
#include <cuda_runtime.h>
#include <cuda_bf16.h>
#include <cstdint>

// 2-layer LSTM, B=4096, H=300, T=64 — ONE persistent kernel over all 128
// cell-steps. tcgen05 bf16-split MMA (hi*hi+hi*lo+lo*hi), D in TMEM fp32.
// Per CTA: M=128 x N=304 (300+4 pad), grid 32x4=128 CTAs (co-resident) with a
// device-wide barrier between cells. RECURRENT PHASE FIRST: the R operand is
// two cells old, so the entire first pipeline stage (B + A) of the next cell
// is prefetched across the barrier, overlapping epilogue+barrier. Epilogue is
// split across all 8 warps (warp w and w+4 share a TMEM subpartition but
// process different column blocks). All SW128 descriptor bases 1024-aligned.

#if defined(__CUDA_ARCH_FEAT_SM103_ALL) || defined(__CUDA_ARCH_FEAT_SM100_ALL) || \
    defined(__CUDA_ARCH_FEAT_SM101_ALL) ||                                        \
    (defined(__CUDA_ARCH_FAMILY_SPECIFIC__) && (__CUDA_ARCH_FAMILY_SPECIFIC__ >= 1000))
#define LSTM_TC 1
#else
#define LSTM_TC 0
#endif

#define SW128(o) ((o) ^ (((o) >> 3) & 0x70))

namespace {
constexpr int Bx = 4096, Hd = 300, Tn = 64;
constexpr int Kp = 320;
constexpr int BM = 128, BNp = 304, BK = 64;
constexpr int NHs = 75;               // real h-groups per CTA
constexpr int NKT = 5;
constexpr int NIT = 10;
constexpr int NMT = Bx / BM;          // 32
constexpr int NNT = 4;
constexpr int CELLS = 2 * Tn;         // 128
constexpr int A_TILE = BM * 128;      // 16384
constexpr int B_TILE = BNp * 128;     // 38912
constexpr int WMAT = NNT * NKT * BNp * BK;
constexpr unsigned IDESC = (1u << 4) | (1u << 7) | (1u << 10) |
                           ((152 / 8) << 17) | ((BM / 16) << 24);  // N=152/MMA
constexpr unsigned long long DESC_BASE =
    (2ull << 61) | (1ull << 46) | (64ull << 32) | (1ull << 16);
// smem head
constexpr int SM_TMEM = 0;
constexpr int SM_FULL = 8;            // 2 mbarriers: 8,16 (A+B combined)
constexpr int SM_DONE = 24;           // 2 mbarriers: 24,32
constexpr int SM_BIAS = 64;           // 2 x 304 floats
constexpr int ST_A_HI = 0;
constexpr int ST_A_LO = A_TILE;
constexpr int ST_B_HI = 2 * A_TILE;
constexpr int ST_B_LO = 2 * A_TILE + B_TILE;
constexpr int STAGE_SZ = 2 * A_TILE + 2 * B_TILE;   // 110592
constexpr int SM_STAGE0 = 4096;
constexpr int SM_TOTAL = SM_STAGE0 + 2 * STAGE_SZ;  // 225280
// epilogue staging lives in STAGE 1 (free after final DONE; stage 0 hosts the
// cross-barrier prefetch)
constexpr int EP_HHI = SM_STAGE0 + STAGE_SZ;
constexpr int EP_HLO = EP_HHI + BM * NHs * 2;
constexpr int EP_Y   = EP_HLO + BM * NHs * 2;
}

// ---- persistent device state -------------------------------------------
__device__ __align__(1024) __nv_bfloat16 g_WHi[4][WMAT];  // ih0,hh0,ih1,hh1
__device__ __align__(1024) __nv_bfloat16 g_WLo[4][WMAT];
__device__ __align__(1024) __nv_bfloat16 g_actHi[5][Bx * Kp];
__device__ __align__(1024) __nv_bfloat16 g_actLo[5][Bx * Kp];
__device__ float g_bias[2][4 * Hd];
__device__ float g_c[2][Hd * Bx];
__device__ unsigned g_bar;

__device__ __forceinline__ float sigmoid_f(float v) {
  return __fdividef(1.0f, 1.0f + __expf(-v));
}
__device__ __forceinline__ float tanh_f(float v) {
  return 2.0f * __fdividef(1.0f, 1.0f + __expf(-2.0f * v)) - 1.0f;
}

__device__ __forceinline__ void grid_barrier(int epoch, int tid) {
  __threadfence();
  __syncthreads();
  if (tid == 0) {
    atomicAdd(&g_bar, 1u);
    const unsigned target = 128u * (unsigned)epoch;
    unsigned v = 0, spins = 0;
    do {
      asm volatile("ld.acquire.gpu.u32 %0, [%1];" : "=r"(v) : "l"(&g_bar)
                   : "memory");
    } while (v < target && ++spins < (1u << 22));
  }
  __syncthreads();
}

#if LSTM_TC
__device__ __forceinline__ void mma_f16_ss(uint32_t d, unsigned long long da,
                                           unsigned long long db, uint32_t en) {
  asm volatile(
      "{\n\t.reg .pred p;\n\tsetp.ne.u32 p, %4, 0;\n\t"
      "tcgen05.mma.cta_group::1.kind::f16 [%0], %1, %2, %3, {%5, %5, %5, %5}, p;\n\t}"
      :: "r"(d), "l"(da), "l"(db), "r"(IDESC), "r"(en), "r"(0u) : "memory");
}
__device__ __forceinline__ void mbar_wait(uint32_t mbar, uint32_t parity) {
  uint32_t done;
  asm volatile(
      "{\n\t.reg .pred p;\n\t"
      "mbarrier.try_wait.parity.acquire.cta.shared::cta.b64 p, [%1], %2;\n\t"
      "selp.b32 %0, 1, 0, p;\n\t}"
      : "=r"(done) : "r"(mbar), "r"(parity) : "memory");
  if (!done) {
    asm volatile(
        "{\n\t.reg .pred P1;\n\t"
        "W_%=:\n\t"
        "mbarrier.try_wait.parity.acquire.cta.shared::cta.b64 P1, [%0], %1, 0x989680;\n\t"
        "@P1 bra.uni D_%=;\n\t"
        "bra.uni W_%=;\n\t"
        "D_%=:\n\t}"
        :: "r"(mbar), "r"(parity) : "memory");
  }
}
__device__ __forceinline__ void bulk_cp(uint32_t dst, const void* src,
                                        uint32_t bytes, uint32_t mbar) {
  asm volatile(
      "cp.async.bulk.shared::cta.global.mbarrier::complete_tx::bytes "
      "[%0], [%1], %2, [%3];"
      :: "r"(dst), "l"(src), "r"(bytes), "r"(mbar) : "memory");
}
__device__ __forceinline__ void expect_tx(uint32_t mbar, uint32_t bytes) {
  asm volatile("mbarrier.arrive.expect_tx.shared.b64 _, [%0], %1;"
               :: "r"(mbar), "r"(bytes) : "memory");
}
__device__ __forceinline__ void ldtm_x32(uint32_t* r, uint32_t a) {
  asm volatile(
      "tcgen05.ld.sync.aligned.32x32b.x32.b32 "
      "{%0,%1,%2,%3,%4,%5,%6,%7,%8,%9,%10,%11,%12,%13,%14,%15,"
      "%16,%17,%18,%19,%20,%21,%22,%23,%24,%25,%26,%27,%28,%29,%30,%31}, [%32];"
      : "=r"(r[0]), "=r"(r[1]), "=r"(r[2]), "=r"(r[3]), "=r"(r[4]), "=r"(r[5]),
        "=r"(r[6]), "=r"(r[7]), "=r"(r[8]), "=r"(r[9]), "=r"(r[10]), "=r"(r[11]),
        "=r"(r[12]), "=r"(r[13]), "=r"(r[14]), "=r"(r[15]), "=r"(r[16]),
        "=r"(r[17]), "=r"(r[18]), "=r"(r[19]), "=r"(r[20]), "=r"(r[21]),
        "=r"(r[22]), "=r"(r[23]), "=r"(r[24]), "=r"(r[25]), "=r"(r[26]),
        "=r"(r[27]), "=r"(r[28]), "=r"(r[29]), "=r"(r[30]), "=r"(r[31])
      : "r"(a));
}
__device__ __forceinline__ void ldtm_x16(uint32_t* r, uint32_t a) {
  asm volatile(
      "tcgen05.ld.sync.aligned.32x32b.x16.b32 "
      "{%0,%1,%2,%3,%4,%5,%6,%7,%8,%9,%10,%11,%12,%13,%14,%15}, [%16];"
      : "=r"(r[0]), "=r"(r[1]), "=r"(r[2]), "=r"(r[3]), "=r"(r[4]), "=r"(r[5]),
        "=r"(r[6]), "=r"(r[7]), "=r"(r[8]), "=r"(r[9]), "=r"(r[10]), "=r"(r[11]),
        "=r"(r[12]), "=r"(r[13]), "=r"(r[14]), "=r"(r[15])
      : "r"(a));
}
#endif  // LSTM_TC

// activation buffer ids for a cell
__device__ __forceinline__ void cell_bufs(int cell, int& xb, int& rb, int& hob) {
  int L = cell & 1, t = cell >> 1, cur = t & 1, nxt = cur ^ 1;
  if (L == 0) {
    xb = (t == 0) ? 0 : (3 + cur);
    rb = 1 + cur;
    hob = 1 + nxt;
  } else {
    xb = 1 + nxt;
    rb = 3 + cur;
    hob = 3 + nxt;
  }
}

// ---- prep ---------------------------------------------------------------
__global__ void prep_kernel(const float* __restrict__ z,
                            const float* __restrict__ Wih0,
                            const float* __restrict__ Whh0,
                            const float* __restrict__ bih0,
                            const float* __restrict__ bhh0,
                            const float* __restrict__ Wih1,
                            const float* __restrict__ Whh1,
                            const float* __restrict__ bih1,
                            const float* __restrict__ bhh1) {
  const int stride = gridDim.x * blockDim.x;
  const int g0 = blockIdx.x * blockDim.x + threadIdx.x;
  if (g0 == 0) g_bar = 0u;
  const float* Ws[4] = {Wih0, Whh0, Wih1, Whh1};
  char* wHiB = (char*)g_WHi;
  char* wLoB = (char*)g_WLo;
  for (int idx = g0; idx < 4 * WMAT; idx += stride) {
    int mi = idx / WMAT;
    int rem = idx - mi * WMAT;
    int tile = rem / (BNp * BK);
    int e = rem - tile * (BNp * BK);
    int r = e / BK, cc = e - (e / BK) * BK;
    int ntt = tile / NKT, ktt = tile - ntt * NKT;
    int k = ktt * BK + cc;
    float w = 0.f;
    if (r < 300 && k < Hd) {
      int n = ntt * 300 + r;
      int h = n >> 2, gg = n & 3;
      w = Ws[mi][(gg * Hd + h) * Hd + k];
    }
    __nv_bfloat16 hi = __float2bfloat16(w);
    size_t off = (size_t)mi * ((size_t)WMAT * 2) + (size_t)tile * B_TILE +
                 SW128(r * 128 + cc * 2);
    *(__nv_bfloat16*)(wHiB + off) = hi;
    *(__nv_bfloat16*)(wLoB + off) = __float2bfloat16(w - __bfloat162float(hi));
  }
  for (int idx = g0; idx < 2 * 4 * Hd; idx += stride) {
    int n = idx % (4 * Hd), cell = idx / (4 * Hd);
    int h = n >> 2, gg = n & 3;
    g_bias[cell][n] = cell ? (bih1[gg * Hd + h] + bhh1[gg * Hd + h])
                           : (bih0[gg * Hd + h] + bhh0[gg * Hd + h]);
  }
  char* aHiB = (char*)g_actHi;
  char* aLoB = (char*)g_actLo;
  for (int idx = g0; idx < Bx * Kp; idx += stride) {
    int k = idx % Kp, m = idx / Kp;
    float v = (k < Hd) ? z[m * Hd + k] : 0.f;
    __nv_bfloat16 hi = __float2bfloat16(v);
    int mt = m / BM, r = m % BM, kt = k / BK, cc = k % BK;
    size_t off = (size_t)(mt * NKT + kt) * A_TILE + SW128(r * 128 + cc * 2);
    *(__nv_bfloat16*)(aHiB + off) = hi;
    *(__nv_bfloat16*)(aLoB + off) = __float2bfloat16(v - __bfloat162float(hi));
  }
  uint4* zh = (uint4*)(g_actHi[1]);
  uint4* zl = (uint4*)(g_actLo[1]);
  const int nq = 4 * Bx * Kp * 2 / 16;
  uint4 zz = {0u, 0u, 0u, 0u};
  for (int idx = g0; idx < nq; idx += stride) { zh[idx] = zz; zl[idx] = zz; }
  for (int idx = g0; idx < Hd * Bx; idx += stride) {
    g_c[0][idx] = 0.f;
    g_c[1][idx] = 0.f;
  }
}

// ---- persistent fused kernel --------------------------------------------
__global__ __launch_bounds__(256) void lstm_persist_kernel(float* __restrict__ Y) {
  extern __shared__ __align__(1024) char smem[];
  const uint32_t sbase = (uint32_t)__cvta_generic_to_shared(smem);
  const int tid = threadIdx.x;
  const int wid = tid >> 5, lid = tid & 31;
  const int mt = blockIdx.x;
  const int nt = blockIdx.y;
  const int m0 = mt * BM;

#if LSTM_TC
  if (wid == 0) {
    asm volatile(
        "tcgen05.alloc.cta_group::1.sync.aligned.shared::cta.b32 [%0], %1;"
        :: "r"(sbase + SM_TMEM), "r"(512u) : "memory");
  }
  if (tid == 0) {
    #pragma unroll
    for (int s = 0; s < 2; ++s) {
      asm volatile("mbarrier.init.shared.b64 [%0], 1;"
                   :: "r"(sbase + SM_FULL + 8 * s) : "memory");
      asm volatile("mbarrier.init.shared.b64 [%0], 1;"
                   :: "r"(sbase + SM_DONE + 8 * s) : "memory");
    }
  }
#endif
  for (int i = tid; i < 2 * BNp; i += 256) {
    int L = i / BNp, col = i - L * BNp;
    float b = (col < 300) ? g_bias[L][nt * 300 + col] : 0.f;
    ((float*)(smem + SM_BIAS))[L * BNp + col] = b;
  }
  __syncthreads();

#if LSTM_TC
  uint32_t tmem_base;
  asm volatile("ld.shared.b32 %0, [%1];"
               : "=r"(tmem_base) : "r"(sbase + SM_TMEM));
  const uint32_t dD = tmem_base;
  const bool l0 = (lid == 0);

  // combined A+B issue. PHASE ORDER: j<NKT = recurrent (Whh, h two cells
  // old -> prefetchable across the barrier); j>=NKT = input phase (Wih, h
  // from previous cell).
  auto issueAB = [&](int G) {
    if (!l0) return;
    int c = G / NIT, j = G - (G / NIT) * NIT;
    int phr = (j < NKT);                 // 1 = recurrent phase
    int kt = phr ? j : (j - NKT);
    int s = j & 1;
    int xb, rb, hob;
    cell_bufs(c, xb, rb, hob);
    int ab = phr ? rb : xb;
    int mi = 2 * (c & 1) + (phr ? 1 : 0);
    const char* ah = (const char*)g_actHi[ab];
    const char* al = (const char*)g_actLo[ab];
    const char* bh = (const char*)g_WHi[mi];
    const char* bl = (const char*)g_WLo[mi];
    uint32_t stb = sbase + SM_STAGE0 + s * STAGE_SZ;
    uint32_t mb = sbase + SM_FULL + 8 * s;
    expect_tx(mb, (uint32_t)STAGE_SZ);
    size_t aoff = (size_t)(mt * NKT + kt) * A_TILE;
    size_t boff = (size_t)(nt * NKT + kt) * B_TILE;
    bulk_cp(stb + ST_A_HI, ah + aoff, A_TILE, mb);
    bulk_cp(stb + ST_A_LO, al + aoff, A_TILE, mb);
    bulk_cp(stb + ST_B_HI, bh + boff, B_TILE, mb);
    bulk_cp(stb + ST_B_LO, bl + boff, B_TILE, mb);
  };

  __nv_bfloat16* hst_hi = (__nv_bfloat16*)(smem + EP_HHI);
  __nv_bfloat16* hst_lo = (__nv_bfloat16*)(smem + EP_HLO);
  float* yst = (float*)(smem + EP_Y);

  #pragma unroll 1
  for (int cell = 0; cell < CELLS; ++cell) {
    const int G0 = cell * NIT;
    const int L = cell & 1, t = cell >> 1;
    int xb, rb, hob;
    cell_bufs(cell, xb, rb, hob);
    float* C = g_c[L];
    const float* bsm = (const float*)(smem + SM_BIAS) + L * BNp;

    if (wid == 0) {
      if (cell == 0) {
        issueAB(0);
        issueAB(1);
      } else {
        // stage 0 (G0) was prefetched pre-barrier; h of previous cell now
        // globally visible -> fence async proxy, then fill stage 1.
        asm volatile("fence.proxy.async;" ::: "memory");
        issueAB(G0 + 1);
      }
      #pragma unroll 1
      for (int j = 0; j < NIT; ++j) {
        const int G = G0 + j;
        const int s = j & 1;
        const uint32_t par = (uint32_t)((G >> 1) & 1);
        mbar_wait(sbase + SM_FULL + 8 * s, par);
        if (l0) {
          const uint32_t stb = sbase + SM_STAGE0 + s * STAGE_SZ;
          unsigned long long dAh = DESC_BASE | (((stb + ST_A_HI) >> 4) & 0x3FFF);
          unsigned long long dAl = DESC_BASE | (((stb + ST_A_LO) >> 4) & 0x3FFF);
          unsigned long long dBh = DESC_BASE | (((stb + ST_B_HI) >> 4) & 0x3FFF);
          unsigned long long dBl = DESC_BASE | (((stb + ST_B_LO) >> 4) & 0x3FFF);
          #pragma unroll
          for (int k16 = 0; k16 < 4; ++k16) {
            unsigned long long off = k16 * 2;
            uint32_t en0 = !(j == 0 && k16 == 0);
            #pragma unroll
            for (int half = 0; half < 2; ++half) {
              unsigned long long bo = off + half * 1216;  // +152 rows
              uint32_t dDh = dD + half * 152;
              mma_f16_ss(dDh, dAh + off, dBh + bo, en0);
              mma_f16_ss(dDh, dAh + off, dBl + bo, 1);
              mma_f16_ss(dDh, dAl + off, dBh + bo, 1);
            }
          }
          asm volatile(
              "tcgen05.commit.cta_group::1.mbarrier::arrive::one.shared::cluster.b64 [%0];"
              :: "r"(sbase + SM_DONE + 8 * s) : "memory");
        }
        if (j <= NIT - 3) {
          mbar_wait(sbase + SM_DONE + 8 * s, par);
          issueAB(G + 2);
        }
      }
      // drain stage0 (j=8), prefetch NEXT cell's stage0 (recurrent phase —
      // safe pre-barrier), then drain stage1 (j=9).
      mbar_wait(sbase + SM_DONE + 0, (uint32_t)(((G0 + 8) >> 1) & 1));
      if (cell < CELLS - 1) issueAB(G0 + NIT);
      mbar_wait(sbase + SM_DONE + 8, (uint32_t)(((G0 + 9) >> 1) & 1));
    }
    __syncthreads();

    // ---- fused LSTM epilogue: ALL 8 warps (grp 0: cbi 0-4, grp 1: 5-9) --
    {
      asm volatile("tcgen05.fence::after_thread_sync;" ::: "memory");
      const int grp = wid >> 2;
      const int ml = (wid & 3) * 32 + lid;
      const int m = m0 + ml;
      const int hg0 = nt * NHs;
      uint32_t r[32];
      #pragma unroll 1
      for (int c5 = 0; c5 < 5; ++c5) {
        const int cbi = grp * 5 + c5;
        const int cb = cbi * 32;
        const int nh = (cbi < 9) ? 8 : 3;
        if (cbi < 9) ldtm_x32(r, dD + cb);
        else         ldtm_x16(r, dD + cb);
        asm volatile("tcgen05.wait::ld.sync.aligned;" ::: "memory");
        #pragma unroll
        for (int j2 = 0; j2 < 8; ++j2) {
          if (j2 >= nh) break;
          const int col = cb + j2 * 4;
          const int hgl = col >> 2;
          float vi = __uint_as_float(r[j2 * 4 + 0]) + bsm[col + 0];
          float vf = __uint_as_float(r[j2 * 4 + 1]) + bsm[col + 1];
          float vg = __uint_as_float(r[j2 * 4 + 2]) + bsm[col + 2];
          float vo = __uint_as_float(r[j2 * 4 + 3]) + bsm[col + 3];
          float i_ = sigmoid_f(vi);
          float f_ = sigmoid_f(vf);
          float g_ = tanh_f(vg);
          float o_ = sigmoid_f(vo);
          size_t ci = (size_t)(hg0 + hgl) * Bx + m;
          float c = f_ * C[ci] + i_ * g_;
          float h = o_ * tanh_f(c);
          C[ci] = c;
          __nv_bfloat16 hi = __float2bfloat16(h);
          hst_hi[ml * NHs + hgl] = hi;
          hst_lo[ml * NHs + hgl] = __float2bfloat16(h - __bfloat162float(hi));
          yst[ml * NHs + hgl] = h;
        }
      }
    }
    __syncthreads();
    // ---- copy-out --------------------------------------------------------
    {
      char* hoHiB = (char*)g_actHi[hob];
      char* hoLoB = (char*)g_actLo[hob];
      for (int e = tid; e < BM * NHs; e += 256) {
        int m2 = e / NHs, j3 = e - (e / NHs) * NHs;
        int hg = nt * NHs + j3;
        int kt2 = hg >> 6, cc = hg & 63;
        size_t off = (size_t)(mt * NKT + kt2) * A_TILE + SW128(m2 * 128 + cc * 2);
        *(__nv_bfloat16*)(hoHiB + off) = hst_hi[e];
        *(__nv_bfloat16*)(hoLoB + off) = hst_lo[e];
      }
      if (L) {
        for (int e = tid; e < BM * NHs; e += 256) {
          int m2 = e / NHs, j3 = e - (e / NHs) * NHs;
          int hg = nt * NHs + j3;
          Y[(size_t)(m0 + m2) * (Tn * Hd) + (size_t)t * Hd + hg] = yst[e];
        }
      }
    }
    if (cell < CELLS - 1) grid_barrier(cell + 1, tid);
  }

  __syncthreads();
  if (tid == 0) {
    #pragma unroll
    for (int s = 0; s < 2; ++s) {
      asm volatile("mbarrier.inval.shared.b64 [%0];"
                   :: "r"(sbase + SM_FULL + 8 * s) : "memory");
      asm volatile("mbarrier.inval.shared.b64 [%0];"
                   :: "r"(sbase + SM_DONE + 8 * s) : "memory");
    }
  }
  if (wid == 0) {
    asm volatile("tcgen05.relinquish_alloc_permit.cta_group::1.sync.aligned;");
    asm volatile("tcgen05.dealloc.cta_group::1.sync.aligned.b32 %0, %1;"
                 :: "r"(tmem_base), "r"(512u));
  }
#else
  // ---- SIMT fallback ----------------------------------------------------
  const int f_row = tid >> 1;
  const int f_ch = tid & 1;
  #pragma unroll 1
  for (int cell = 0; cell < CELLS; ++cell) {
    const int L = cell & 1, t = cell >> 1;
    int xb, rb, hob;
    cell_bufs(cell, xb, rb, hob);
    float* C = g_c[L];
    const float* bsm = (const float*)(smem + SM_BIAS) + L * BNp;
    float facc[152];
    for (int i = 0; i < 152; ++i) facc[i] = 0.f;
    for (int it = 0; it < NIT; ++it) {
      int phr = (it < NKT), ktt = phr ? it : (it - NKT);
      int ab = phr ? rb : xb;
      int mi = 2 * L + (phr ? 1 : 0);
      const char* ah = (const char*)g_actHi[ab];
      const char* al = (const char*)g_actLo[ab];
      const char* bh = (const char*)g_WHi[mi];
      const char* bl = (const char*)g_WLo[mi];
      size_t at = (size_t)(mt * NKT + ktt) * A_TILE;
      size_t bt = (size_t)(nt * NKT + ktt) * B_TILE;
      for (int k = 0; k < BK; ++k) {
        uint32_t ao = SW128(f_row * 128 + k * 2);
        float a = __bfloat162float(*(const __nv_bfloat16*)(ah + at + ao)) +
                  __bfloat162float(*(const __nv_bfloat16*)(al + at + ao));
        for (int c2 = 0; c2 < 152; ++c2) {
          int bn = f_ch * 152 + c2;
          uint32_t bo = SW128(bn * 128 + k * 2);
          float b = __bfloat162float(*(const __nv_bfloat16*)(bh + bt + bo)) +
                    __bfloat162float(*(const __nv_bfloat16*)(bl + bt + bo));
          facc[c2] = fmaf(a, b, facc[c2]);
        }
      }
    }
    {
      char* hoHiB = (char*)g_actHi[hob];
      char* hoLoB = (char*)g_actLo[hob];
      const int m = m0 + f_row;
      for (int jh = 0; jh < 38; ++jh) {
        int col = f_ch * 152 + jh * 4;
        if (col >= 300) break;
        int hg = nt * NHs + (col >> 2);
        float i_ = sigmoid_f(facc[jh * 4 + 0] + bsm[col + 0]);
        float f_ = sigmoid_f(facc[jh * 4 + 1] + bsm[col + 1]);
        float g_ = tanh_f(facc[jh * 4 + 2] + bsm[col + 2]);
        float o_ = sigmoid_f(facc[jh * 4 + 3] + bsm[col + 3]);
        size_t ci = (size_t)hg * Bx + m;
        float c = f_ * C[ci] + i_ * g_;
        float h = o_ * tanh_f(c);
        C[ci] = c;
        int kt2 = hg >> 6, cc = hg & 63;
        size_t off = (size_t)(mt * NKT + kt2) * A_TILE + SW128(f_row * 128 + cc * 2);
        __nv_bfloat16 hi = __float2bfloat16(h);
        *(__nv_bfloat16*)(hoHiB + off) = hi;
        *(__nv_bfloat16*)(hoLoB + off) =
            __float2bfloat16(h - __bfloat162float(hi));
        if (L) Y[(size_t)m * (Tn * Hd) + (size_t)t * Hd + hg] = h;
      }
    }
    if (cell < CELLS - 1) grid_barrier(cell + 1, tid);
  }
#endif
}

// ---- host side ----------------------------------------------------------
extern "C" void kernel_launch(void* const* d_in, const int* in_sizes, int n_in,
                              void* d_out, int out_size) {
  const float* z    = (const float*)d_in[0];
  const float* Wih0 = (const float*)d_in[1];
  const float* Whh0 = (const float*)d_in[2];
  const float* bih0 = (const float*)d_in[3];
  const float* bhh0 = (const float*)d_in[4];
  const float* Wih1 = (const float*)d_in[5];
  const float* Whh1 = (const float*)d_in[6];
  const float* bih1 = (const float*)d_in[7];
  const float* bhh1 = (const float*)d_in[8];
  float* out = (float*)d_out;

  cudaFuncSetAttribute(lstm_persist_kernel,
                       cudaFuncAttributeMaxDynamicSharedMemorySize, SM_TOTAL);

  prep_kernel<<<1024, 256>>>(z, Wih0, Whh0, bih0, bhh0, Wih1, Whh1, bih1, bhh1);

  dim3 grid(NMT, NNT);  // 32 x 4 = 128 co-resident CTAs
  lstm_persist_kernel<<<grid, 256, SM_TOTAL>>>(out);
}